// round 2
// baseline (speedup 1.0000x reference)
#include <cuda_runtime.h>
#include <math.h>

// ---------------- problem constants (fixed shapes) ----------------
#define BB   8
#define TT   2048
#define CC   1024
#define RR   64
#define ARR  32
#define FFD  4096
#define MM   (BB*TT)        // 16384 rows
#define SEG  16
#define LSEG (TT/SEG)       // 128
#define BC   (BB*CC)        // 8192 channels

// ---------------- scratch (static device globals; no allocs) ------
__device__ float g_xn[MM*CC];     // LN(LN(x))
__device__ float g_qr[MM*RR];
__device__ float g_kr[MM*RR];
__device__ float g_vr[MM*RR];
__device__ float g_q [MM*CC];     // q, then reused in-place as ys
__device__ float g_k [MM*CC];
__device__ float g_v [MM*CC];
__device__ float g_x1[MM*CC];     // x + attn
__device__ float g_h2[MM*CC];     // LN2(x1)
__device__ float g_ff[MM*FFD];    // gelu(h2@w1+b1)
__device__ float g_x2[MM*CC];     // after FFN residual
__device__ float g_ad[MM*ARR];    // adapter bottleneck
__device__ float g_hloc[SEG*BC];
__device__ float g_hin [SEG*BC];

// ---------------- helpers -----------------------------------------
__device__ __forceinline__ float gelu_tanh(float x) {
    // jax.nn.gelu default (approximate=True)
    float x3 = x * x * x;
    return 0.5f * x * (1.f + tanhf(0.7978845608028654f * (x + 0.044715f * x3)));
}

// block-wide sum for 256 threads; sh must hold >= 8 floats.
// FIX vs round 1: broadcast the final sum to ALL lanes (previously lanes
// 8..31 of each warp returned 0, corrupting every LayerNorm).
__device__ __forceinline__ float block_sum_256(float val, float* sh) {
    int lane = threadIdx.x & 31;
#pragma unroll
    for (int o = 16; o > 0; o >>= 1) val += __shfl_xor_sync(0xffffffffu, val, o);
    if (lane == 0) sh[threadIdx.x >> 5] = val;
    __syncthreads();
    float r = (lane < 8) ? sh[lane] : 0.f;
#pragma unroll
    for (int o = 4; o > 0; o >>= 1) r += __shfl_xor_sync(0xffffffffu, r, o);
    r = __shfl_sync(0xffffffffu, r, 0);   // broadcast to all 32 lanes
    __syncthreads();   // protect sh for subsequent calls
    return r;
}

// ---------------- LayerNorm (optionally chained twice) ------------
// one block per row of C=1024, 256 threads, 4 elems/thread
__global__ void ln_kernel(const float* __restrict__ x,
                          const float* __restrict__ g1, const float* __restrict__ b1,
                          const float* __restrict__ g2, const float* __restrict__ b2,
                          float* __restrict__ out)
{
    __shared__ float sh[8];
    int row = blockIdx.x;
    int tid = threadIdx.x;
    const float* xr = x + (size_t)row * CC;
    float v[4];
#pragma unroll
    for (int i = 0; i < 4; i++) v[i] = xr[tid + i * 256];

#pragma unroll 1
    for (int pass = 0; pass < 2; pass++) {
        const float* gg = pass ? g2 : g1;
        const float* bb = pass ? b2 : b1;
        if (gg == nullptr) break;
        float s = v[0] + v[1] + v[2] + v[3];
        float mean = block_sum_256(s, sh) * (1.f / CC);
        float s2 = 0.f;
#pragma unroll
        for (int i = 0; i < 4; i++) { float d = v[i] - mean; s2 += d * d; }
        float var = block_sum_256(s2, sh) * (1.f / CC);
        float rstd = rsqrtf(var + 1e-5f);
#pragma unroll
        for (int i = 0; i < 4; i++) {
            int idx = tid + i * 256;
            v[i] = (v[i] - mean) * rstd * gg[idx] + bb[idx];
        }
    }
    float* orow = out + (size_t)row * CC;
#pragma unroll
    for (int i = 0; i < 4; i++) orow[tid + i * 256] = v[i];
}

// ---------------- generic tiled SGEMM ------------------------------
// C[M,N] = op(A[M,K] @ B[K,N]); A,B,C row-major.
// MIXA: A element is 0.5*(xn[row] + xn[row-1]) (token shift, t=row%TT).
// Epilogue: (+bias[col]) -> (gelu) -> (+res[row,col])
template<int BM, int BN, int BK, int TM, int TN,
         bool MIXA, bool BIAS, bool GELU, bool RES>
__global__ void __launch_bounds__((BM/TM)*(BN/TN))
sgemm_kernel(int M, int N, int K,
             const float* __restrict__ A, const float* __restrict__ B,
             float* __restrict__ C,
             const float* __restrict__ bias, const float* __restrict__ res)
{
    constexpr int NT = (BM / TM) * (BN / TN);
    __shared__ float As[BK][BM];
    __shared__ float Bs[BK][BN];
    const int tid  = threadIdx.x;
    const int brow = blockIdx.y * BM;
    const int bcol = blockIdx.x * BN;
    const int tr   = tid / (BN / TN);
    const int tc   = tid % (BN / TN);

    float acc[TM][TN];
#pragma unroll
    for (int i = 0; i < TM; i++)
#pragma unroll
        for (int j = 0; j < TN; j++) acc[i][j] = 0.f;

    for (int k0 = 0; k0 < K; k0 += BK) {
        // load A tile (transposed into As[k][m]), float4 along K
#pragma unroll
        for (int i = tid; i < BM * (BK / 4); i += NT) {
            int m  = i / (BK / 4);
            int kq = (i % (BK / 4)) * 4;
            const float* ap = A + (size_t)(brow + m) * K + k0 + kq;
            float4 av = *(const float4*)ap;
            if (MIXA) {
                int t = (brow + m) & (TT - 1);   // TT is pow2
                float4 pv = make_float4(0.f, 0.f, 0.f, 0.f);
                if (t > 0) pv = *(const float4*)(ap - K);
                av.x = 0.5f * (av.x + pv.x); av.y = 0.5f * (av.y + pv.y);
                av.z = 0.5f * (av.z + pv.z); av.w = 0.5f * (av.w + pv.w);
            }
            As[kq + 0][m] = av.x; As[kq + 1][m] = av.y;
            As[kq + 2][m] = av.z; As[kq + 3][m] = av.w;
        }
        // load B tile, float4 along N
#pragma unroll
        for (int i = tid; i < BK * (BN / 4); i += NT) {
            int kk = i / (BN / 4);
            int nq = (i % (BN / 4)) * 4;
            float4 bv = *(const float4*)(B + (size_t)(k0 + kk) * N + bcol + nq);
            *(float4*)&Bs[kk][nq] = bv;
        }
        __syncthreads();

#pragma unroll
        for (int kk = 0; kk < BK; kk++) {
            float ra[TM], rb[TN];
#pragma unroll
            for (int i = 0; i < TM; i++) ra[i] = As[kk][tr * TM + i];
#pragma unroll
            for (int j = 0; j < TN; j++) rb[j] = Bs[kk][tc * TN + j];
#pragma unroll
            for (int i = 0; i < TM; i++)
#pragma unroll
                for (int j = 0; j < TN; j++) acc[i][j] += ra[i] * rb[j];
        }
        __syncthreads();
    }

#pragma unroll
    for (int i = 0; i < TM; i++) {
        int grow = brow + tr * TM + i;
#pragma unroll
        for (int j = 0; j < TN; j++) {
            int gcol = bcol + tc * TN + j;
            float c = acc[i][j];
            if (BIAS) c += bias[gcol];
            if (GELU) c = gelu_tanh(c);
            if (RES)  c += res[(size_t)grow * N + gcol];
            C[(size_t)grow * N + gcol] = c;
        }
    }
}

// ---------------- segmented scan ------------------------------------
// h_t = d*h_{t-1} + k_t*v_t ; y_t = sigmoid(q_t)*h_t ; d = exp(-exp(td[c]))
__global__ void scan_local(const float* __restrict__ k, const float* __restrict__ v,
                           const float* __restrict__ td, float* __restrict__ hloc)
{
    int idx = blockIdx.x * blockDim.x + threadIdx.x;     // < SEG*BC
    int seg = idx / BC;
    int rem = idx - seg * BC;
    int b   = rem / CC;
    int c   = rem - b * CC;
    float d = expf(-expf(td[c]));
    size_t base = ((size_t)(b * TT + seg * LSEG)) * CC + c;
    float h = 0.f;
#pragma unroll 4
    for (int i = 0; i < LSEG; i++) {
        h = d * h + k[base] * v[base];
        base += CC;
    }
    hloc[idx] = h;
}

__global__ void scan_combine(const float* __restrict__ hloc, const float* __restrict__ h0,
                             const float* __restrict__ td, float* __restrict__ hin,
                             float* __restrict__ out, long out_size)
{
    int rem = blockIdx.x * blockDim.x + threadIdx.x;     // < BC
    int c = rem & (CC - 1);
    float e  = expf(td[c]);
    float dL = expf(-(float)LSEG * e);                   // decay^LSEG exactly
    float h = h0[rem];
#pragma unroll
    for (int s = 0; s < SEG; s++) {
        hin[s * BC + rem] = h;
        h = dL * h + hloc[s * BC + rem];
    }
    if (out_size >= (long)MM * CC + BC)
        out[(size_t)MM * CC + rem] = h;                  // h_final
}

__global__ void scan_apply(const float* __restrict__ k, const float* __restrict__ v,
                           const float* __restrict__ q, const float* __restrict__ td,
                           const float* __restrict__ hin, float* __restrict__ y)
{
    int idx = blockIdx.x * blockDim.x + threadIdx.x;     // < SEG*BC
    int seg = idx / BC;
    int rem = idx - seg * BC;
    int b   = rem / CC;
    int c   = rem - b * CC;
    float d = expf(-expf(td[c]));
    float h = hin[seg * BC + rem];
    size_t base = ((size_t)(b * TT + seg * LSEG)) * CC + c;
#pragma unroll 4
    for (int i = 0; i < LSEG; i++) {
        float kv = k[base] * v[base];
        h = d * h + kv;
        float qq = q[base];
        y[base] = h / (1.f + expf(-qq));                 // safe: y aliases q per-element
        base += CC;
    }
}

// ---------------- launch --------------------------------------------
extern "C" void kernel_launch(void* const* d_in, const int* in_sizes, int n_in,
                              void* d_out, int out_size)
{
    const float* x     = (const float*)d_in[0];
    const float* h0    = (const float*)d_in[1];
    const float* ln1_g = (const float*)d_in[2];
    const float* ln1_b = (const float*)d_in[3];
    const float* tm_g  = (const float*)d_in[4];
    const float* tm_b  = (const float*)d_in[5];
    const float* qu    = (const float*)d_in[6];
    const float* qv    = (const float*)d_in[7];
    const float* ku    = (const float*)d_in[8];
    const float* kvw   = (const float*)d_in[9];
    const float* vu    = (const float*)d_in[10];
    const float* vvw   = (const float*)d_in[11];
    const float* td    = (const float*)d_in[12];
    const float* out_w = (const float*)d_in[13];
    const float* out_b = (const float*)d_in[14];
    const float* ln2_g = (const float*)d_in[15];
    const float* ln2_b = (const float*)d_in[16];
    const float* w1    = (const float*)d_in[17];
    const float* b1    = (const float*)d_in[18];
    const float* w2    = (const float*)d_in[19];
    const float* b2    = (const float*)d_in[20];
    const float* adw   = (const float*)d_in[21];
    const float* adb   = (const float*)d_in[22];
    const float* auw   = (const float*)d_in[23];
    const float* aub   = (const float*)d_in[24];
    float* out = (float*)d_out;

    void* p;
    cudaGetSymbolAddress(&p, g_xn);   float* xn  = (float*)p;
    cudaGetSymbolAddress(&p, g_qr);   float* qr  = (float*)p;
    cudaGetSymbolAddress(&p, g_kr);   float* kr  = (float*)p;
    cudaGetSymbolAddress(&p, g_vr);   float* vr  = (float*)p;
    cudaGetSymbolAddress(&p, g_q);    float* q   = (float*)p;
    cudaGetSymbolAddress(&p, g_k);    float* k   = (float*)p;
    cudaGetSymbolAddress(&p, g_v);    float* v   = (float*)p;
    cudaGetSymbolAddress(&p, g_x1);   float* x1  = (float*)p;
    cudaGetSymbolAddress(&p, g_h2);   float* h2  = (float*)p;
    cudaGetSymbolAddress(&p, g_ff);   float* ff  = (float*)p;
    cudaGetSymbolAddress(&p, g_x2);   float* x2  = (float*)p;
    cudaGetSymbolAddress(&p, g_ad);   float* ad  = (float*)p;
    cudaGetSymbolAddress(&p, g_hloc); float* hlc = (float*)p;
    cudaGetSymbolAddress(&p, g_hin);  float* hin = (float*)p;

    // 1) xn = LN(LN(x, ln1), tm_ln)
    ln_kernel<<<MM, 256>>>(x, ln1_g, ln1_b, tm_g, tm_b, xn);

    // 2) low-rank down-projections on mix (mix computed on the fly from xn)
    sgemm_kernel<128, 64, 8, 8, 4, true, false, false, false>
        <<<dim3(RR / 64, MM / 128), 256>>>(MM, RR, CC, xn, qu, qr, nullptr, nullptr);
    sgemm_kernel<128, 64, 8, 8, 4, true, false, false, false>
        <<<dim3(RR / 64, MM / 128), 256>>>(MM, RR, CC, xn, ku, kr, nullptr, nullptr);
    sgemm_kernel<128, 64, 8, 8, 4, true, false, false, false>
        <<<dim3(RR / 64, MM / 128), 256>>>(MM, RR, CC, xn, vu, vr, nullptr, nullptr);

    // 3) up-projections (K=64)
    sgemm_kernel<128, 128, 8, 8, 8, false, false, false, false>
        <<<dim3(CC / 128, MM / 128), 256>>>(MM, CC, RR, qr, qv, q, nullptr, nullptr);
    sgemm_kernel<128, 128, 8, 8, 8, false, false, false, false>
        <<<dim3(CC / 128, MM / 128), 256>>>(MM, CC, RR, kr, kvw, k, nullptr, nullptr);
    sgemm_kernel<128, 128, 8, 8, 8, false, false, false, false>
        <<<dim3(CC / 128, MM / 128), 256>>>(MM, CC, RR, vr, vvw, v, nullptr, nullptr);

    // 4) segmented scan: local -> combine -> apply (ys written in-place over q)
    scan_local  <<<(SEG * BC) / 256, 256>>>(k, v, td, hlc);
    scan_combine<<<BC / 256, 256>>>(hlc, h0, td, hin, out, (long)out_size);
    scan_apply  <<<(SEG * BC) / 256, 256>>>(k, v, q, td, hin, q);

    // 5) attn out-proj + residual with original x
    sgemm_kernel<128, 128, 8, 8, 8, false, true, false, true>
        <<<dim3(CC / 128, MM / 128), 256>>>(MM, CC, CC, q, out_w, x1, out_b, x);

    // 6) h2 = LN(x1)
    ln_kernel<<<MM, 256>>>(x1, ln2_g, ln2_b, nullptr, nullptr, h2);

    // 7) FFN
    sgemm_kernel<128, 128, 8, 8, 8, false, true, true, false>
        <<<dim3(FFD / 128, MM / 128), 256>>>(MM, FFD, CC, h2, w1, ff, b1, nullptr);
    sgemm_kernel<128, 128, 8, 8, 8, false, true, false, true>
        <<<dim3(CC / 128, MM / 128), 256>>>(MM, CC, FFD, ff, w2, x2, b2, x1);

    // 8) adapter
    sgemm_kernel<128, 32, 8, 8, 2, false, true, true, false>
        <<<dim3(ARR / 32, MM / 128), 256>>>(MM, ARR, CC, x2, adw, ad, adb, nullptr);
    sgemm_kernel<128, 128, 8, 8, 8, false, true, false, true>
        <<<dim3(CC / 128, MM / 128), 256>>>(MM, CC, ARR, ad, auw, out, aub, x2);
}

// round 4
// speedup vs baseline: 3.1797x; 3.1797x over previous
#include <cuda_runtime.h>
#include <cuda_bf16.h>
#include <math.h>
#include <stdint.h>

// ---------------- problem constants (fixed shapes) ----------------
#define BB   8
#define TT   2048
#define CC   1024
#define RR   64
#define ARR  32
#define FFD  4096
#define MM   (BB*TT)        // 16384 rows
#define SEG  16
#define LSEG (TT/SEG)       // 128
#define BC   (BB*CC)        // 8192 channels

typedef __nv_bfloat16 bf16;

// ---------------- scratch (static device globals; no allocs) ------
__device__ __align__(256) float g_xn[MM*CC];
__device__ __align__(256) float g_q [MM*CC];
__device__ __align__(256) float g_k [MM*CC];
__device__ __align__(256) float g_v [MM*CC];
__device__ __align__(256) float g_x1[MM*CC];
__device__ __align__(256) float g_x2[MM*CC];
__device__ __align__(256) float g_hloc[SEG*BC];
__device__ __align__(256) float g_hin [SEG*BC];

// bf16 hi/lo activation buffers
__device__ __align__(256) bf16 g_mix_h[MM*CC],  g_mix_l[MM*CC];
__device__ __align__(256) bf16 g_qr_h[MM*RR],   g_qr_l[MM*RR];
__device__ __align__(256) bf16 g_kr_h[MM*RR],   g_kr_l[MM*RR];
__device__ __align__(256) bf16 g_vr_h[MM*RR],   g_vr_l[MM*RR];
__device__ __align__(256) bf16 g_ys_h[MM*CC],   g_ys_l[MM*CC];
__device__ __align__(256) bf16 g_h2_h[MM*CC],   g_h2_l[MM*CC];
__device__ __align__(256) bf16 g_ff_h[(size_t)MM*FFD], g_ff_l[(size_t)MM*FFD];
__device__ __align__(256) bf16 g_x2h[MM*CC],    g_x2l[MM*CC];
__device__ __align__(256) bf16 g_ad_h[MM*64],   g_ad_l[MM*64];    // K padded 32->64

// bf16 hi/lo transposed weights  ([N,K] K-major)
__device__ __align__(256) bf16 g_quT_h[RR*CC],  g_quT_l[RR*CC];
__device__ __align__(256) bf16 g_kuT_h[RR*CC],  g_kuT_l[RR*CC];
__device__ __align__(256) bf16 g_vuT_h[RR*CC],  g_vuT_l[RR*CC];
__device__ __align__(256) bf16 g_qvT_h[CC*RR],  g_qvT_l[CC*RR];
__device__ __align__(256) bf16 g_kvT_h[CC*RR],  g_kvT_l[CC*RR];
__device__ __align__(256) bf16 g_vvT_h[CC*RR],  g_vvT_l[CC*RR];
__device__ __align__(256) bf16 g_owT_h[CC*CC],  g_owT_l[CC*CC];
__device__ __align__(256) bf16 g_w1T_h[(size_t)FFD*CC], g_w1T_l[(size_t)FFD*CC];
__device__ __align__(256) bf16 g_w2T_h[(size_t)CC*FFD], g_w2T_l[(size_t)CC*FFD];
__device__ __align__(256) bf16 g_adwT_h[ARR*CC],g_adwT_l[ARR*CC];
__device__ __align__(256) bf16 g_auwT_h[CC*64], g_auwT_l[CC*64];  // K padded 32->64

// ---------------- PTX helpers (sm_80-class only: mma.sync/ldmatrix/cp.async)
__device__ __forceinline__ uint32_t smem_u32(const void* p) {
    uint32_t a;
    asm("{ .reg .u64 t; cvta.to.shared.u64 t, %1; cvt.u32.u64 %0, t; }" : "=r"(a) : "l"(p));
    return a;
}
#define SWZ128(b) ((b) ^ (((b) >> 3) & 0x70))

__device__ __forceinline__ void cp16(uint32_t dst, const void* src) {
    asm volatile("cp.async.cg.shared.global [%0], [%1], 16;" :: "r"(dst), "l"(src));
}
#define CP_COMMIT()  asm volatile("cp.async.commit_group;" ::: "memory")
#define CP_WAIT(n)   asm volatile("cp.async.wait_group %0;" :: "n"(n) : "memory")

__device__ __forceinline__ void ldsm_x4(uint32_t* r, uint32_t addr) {
    asm volatile("ldmatrix.sync.aligned.m8n8.x4.shared.b16 {%0,%1,%2,%3}, [%4];"
                 : "=r"(r[0]), "=r"(r[1]), "=r"(r[2]), "=r"(r[3]) : "r"(addr));
}
__device__ __forceinline__ void mma16816(float* d, const uint32_t* a, const uint32_t* b) {
    asm volatile("mma.sync.aligned.m16n8k16.row.col.f32.bf16.bf16.f32 "
                 "{%0,%1,%2,%3}, {%4,%5,%6,%7}, {%8,%9}, {%0,%1,%2,%3};"
                 : "+f"(d[0]), "+f"(d[1]), "+f"(d[2]), "+f"(d[3])
                 : "r"(a[0]), "r"(a[1]), "r"(a[2]), "r"(a[3]), "r"(b[0]), "r"(b[1]));
}
__device__ __forceinline__ float tanh_fast(float x) {
    float y;
    asm("tanh.approx.f32 %0, %1;" : "=f"(y) : "f"(x));
    return y;
}

// ---------------- misc helpers -------------------------------------
__device__ __forceinline__ float gelu_tanh(float x) {
    float x3 = x * x * x;
    return 0.5f * x * (1.f + tanh_fast(0.7978845608028654f * (x + 0.044715f * x3)));
}
__device__ __forceinline__ float sigmoid_fast(float x) {
    return 0.5f + 0.5f * tanh_fast(0.5f * x);
}
__device__ __forceinline__ void split2(float x, bf16& h, bf16& l) {
    h = __float2bfloat16(x);
    l = __float2bfloat16(x - __bfloat162float(h));
}
__device__ __forceinline__ float block_sum_256(float val, float* sh) {
    int lane = threadIdx.x & 31;
#pragma unroll
    for (int o = 16; o > 0; o >>= 1) val += __shfl_xor_sync(0xffffffffu, val, o);
    if (lane == 0) sh[threadIdx.x >> 5] = val;
    __syncthreads();
    float r = (lane < 8) ? sh[lane] : 0.f;
#pragma unroll
    for (int o = 4; o > 0; o >>= 1) r += __shfl_xor_sync(0xffffffffu, r, o);
    r = __shfl_sync(0xffffffffu, r, 0);
    __syncthreads();
    return r;
}

// ---------------- LayerNorm ----------------------------------------
__global__ void ln_kernel(const float* __restrict__ x,
                          const float* __restrict__ g1, const float* __restrict__ b1,
                          const float* __restrict__ g2, const float* __restrict__ b2,
                          float* __restrict__ out,
                          bf16* __restrict__ oh, bf16* __restrict__ ol)
{
    __shared__ float sh[8];
    int row = blockIdx.x;
    int tid = threadIdx.x;
    const float* xr = x + (size_t)row * CC;
    float v[4];
#pragma unroll
    for (int i = 0; i < 4; i++) v[i] = xr[tid + i * 256];

#pragma unroll 1
    for (int pass = 0; pass < 2; pass++) {
        const float* gg = pass ? g2 : g1;
        const float* bb = pass ? b2 : b1;
        if (gg == nullptr) break;
        float s = v[0] + v[1] + v[2] + v[3];
        float mean = block_sum_256(s, sh) * (1.f / CC);
        float s2 = 0.f;
#pragma unroll
        for (int i = 0; i < 4; i++) { float d = v[i] - mean; s2 += d * d; }
        float var = block_sum_256(s2, sh) * (1.f / CC);
        float rstd = rsqrtf(var + 1e-5f);
#pragma unroll
        for (int i = 0; i < 4; i++) {
            int idx = tid + i * 256;
            v[i] = (v[i] - mean) * rstd * gg[idx] + bb[idx];
        }
    }
#pragma unroll
    for (int i = 0; i < 4; i++) {
        size_t o = (size_t)row * CC + tid + i * 256;
        if (out) out[o] = v[i];
        if (oh) { bf16 h, l; split2(v[i], h, l); oh[o] = h; ol[o] = l; }
    }
}

// ---------------- mix + split --------------------------------------
__global__ void mix_split(const float* __restrict__ xn,
                          bf16* __restrict__ mh, bf16* __restrict__ ml)
{
    size_t i = ((size_t)blockIdx.x * 256 + threadIdx.x) * 4;
    int row = (int)(i >> 10);
    int t = row & (TT - 1);
    float4 a = *(const float4*)(xn + i);
    float4 p = make_float4(0.f, 0.f, 0.f, 0.f);
    if (t > 0) p = *(const float4*)(xn + i - CC);
    float m[4] = {0.5f*(a.x+p.x), 0.5f*(a.y+p.y), 0.5f*(a.z+p.z), 0.5f*(a.w+p.w)};
#pragma unroll
    for (int j = 0; j < 4; j++) { bf16 h, l; split2(m[j], h, l); mh[i+j] = h; ml[i+j] = l; }
}

// ---------------- weight transpose + split -------------------------
__global__ void transpose_split(const float* __restrict__ w, int R, int S, int ldout,
                                bf16* __restrict__ th, bf16* __restrict__ tl)
{
    __shared__ float t[32][33];
    int s0 = blockIdx.x * 32, r0 = blockIdx.y * 32;
#pragma unroll
    for (int i = threadIdx.y; i < 32; i += 8) {
        float v = 0.f;
        if (r0 + i < R) v = w[(size_t)(r0 + i) * S + s0 + threadIdx.x];
        t[i][threadIdx.x] = v;
    }
    __syncthreads();
#pragma unroll
    for (int i = threadIdx.y; i < 32; i += 8) {
        float v = t[threadIdx.x][i];
        size_t o = (size_t)(s0 + i) * ldout + r0 + threadIdx.x;
        bf16 h, l; split2(v, h, l);
        th[o] = h; tl[o] = l;
    }
}

// ---------------- HMMA bf16x3 GEMM ----------------------------------
// D[M,N] = A[M,K] @ B[N,K]^T ; A,B as bf16 (hi,lo) pairs; fp32 accum via
// mma.sync m16n8k16, 3 passes: Ah*Bh + Ah*Bl + Al*Bh.
// BM=128 fixed, BK=64 (SW128 smem rows), cp.async double buffer.
template<int BN, int WMS, int WNS, bool BIAS, bool GELU, bool RES, bool OUTF32, bool OUTBF>
__global__ void __launch_bounds__(256, 1)
mm_bf16(int M, int N, int K, int ldbf,
        const bf16* __restrict__ Ah, const bf16* __restrict__ Al,
        const bf16* __restrict__ Bh, const bf16* __restrict__ Bl,
        float* __restrict__ C, bf16* __restrict__ Ch, bf16* __restrict__ Cl,
        const float* __restrict__ bias, const float* __restrict__ res)
{
    constexpr int BM = 128;
    constexpr int TMW = BM / WMS;      // warp tile rows
    constexpr int TNW = BN / WNS;      // warp tile cols
    constexpr int MT = TMW / 16;       // m16 tiles per warp
    constexpr int NT = TNW / 8;        // n8 tiles per warp (always 4 here)
    constexpr int A_BYTES = BM * 128;  // one matrix tile (hi or lo)
    constexpr int B_BYTES = BN * 128;
    constexpr int STAGE   = 2 * A_BYTES + 2 * B_BYTES;

    extern __shared__ char smem[];
    const uint32_t sb = smem_u32(smem);

    const int tid  = threadIdx.x;
    const int lane = tid & 31;
    const int warp = tid >> 5;
    const int wm   = warp / WNS;
    const int wn   = warp % WNS;
    const int brow = blockIdx.y * BM;
    const int bcol = blockIdx.x * BN;
    const int NK   = K >> 6;

    float acc[MT][NT][4];
#pragma unroll
    for (int i = 0; i < MT; i++)
#pragma unroll
        for (int j = 0; j < NT; j++)
#pragma unroll
            for (int e = 0; e < 4; e++) acc[i][j][e] = 0.f;

    auto load_stage = [&](int kc, int s) {
        uint32_t base = sb + s * STAGE;
#pragma unroll 2
        for (int i = tid; i < BM * 8; i += 256) {
            int r = i >> 3, j = i & 7;
            size_t go = (size_t)(brow + r) * K + (size_t)kc * 64 + j * 8;
            uint32_t sw = SWZ128((uint32_t)(r * 128 + j * 16));
            cp16(base + sw, Ah + go);
            cp16(base + A_BYTES + sw, Al + go);
        }
#pragma unroll 2
        for (int i = tid; i < BN * 8; i += 256) {
            int r = i >> 3, j = i & 7;
            size_t go = (size_t)(bcol + r) * K + (size_t)kc * 64 + j * 8;
            uint32_t sw = SWZ128((uint32_t)(r * 128 + j * 16));
            cp16(base + 2 * A_BYTES + sw, Bh + go);
            cp16(base + 2 * A_BYTES + B_BYTES + sw, Bl + go);
        }
        CP_COMMIT();
    };

    load_stage(0, 0);

    for (int kc = 0; kc < NK; kc++) {
        if (kc + 1 < NK) { load_stage(kc + 1, (kc + 1) & 1); CP_WAIT(1); }
        else             { CP_WAIT(0); }
        __syncthreads();

        const uint32_t st = sb + (kc & 1) * STAGE;
#pragma unroll
        for (int ks = 0; ks < 4; ks++) {
            uint32_t a_h[MT][4], a_l[MT][4];
#pragma unroll
            for (int mt = 0; mt < MT; mt++) {
                int r = wm * TMW + mt * 16 + (lane & 15);
                uint32_t off = SWZ128((uint32_t)(r * 128 + ks * 32 + ((lane >> 4) << 4)));
                ldsm_x4(a_h[mt], st + off);
                ldsm_x4(a_l[mt], st + A_BYTES + off);
            }
            uint32_t b_h[NT][2], b_l[NT][2];
#pragma unroll
            for (int p = 0; p < NT / 2; p++) {
                int r = wn * TNW + p * 16 + (lane & 7) + ((lane >> 4) << 3);
                uint32_t off = SWZ128((uint32_t)(r * 128 + ks * 32 + (((lane >> 3) & 1) << 4)));
                uint32_t t4[4];
                ldsm_x4(t4, st + 2 * A_BYTES + off);
                b_h[2*p][0] = t4[0]; b_h[2*p][1] = t4[1];
                b_h[2*p+1][0] = t4[2]; b_h[2*p+1][1] = t4[3];
                ldsm_x4(t4, st + 2 * A_BYTES + B_BYTES + off);
                b_l[2*p][0] = t4[0]; b_l[2*p][1] = t4[1];
                b_l[2*p+1][0] = t4[2]; b_l[2*p+1][1] = t4[3];
            }
            // pass 1: Ah*Bh
#pragma unroll
            for (int mt = 0; mt < MT; mt++)
#pragma unroll
                for (int nt = 0; nt < NT; nt++) mma16816(acc[mt][nt], a_h[mt], b_h[nt]);
            // pass 2: Ah*Bl
#pragma unroll
            for (int mt = 0; mt < MT; mt++)
#pragma unroll
                for (int nt = 0; nt < NT; nt++) mma16816(acc[mt][nt], a_h[mt], b_l[nt]);
            // pass 3: Al*Bh
#pragma unroll
            for (int mt = 0; mt < MT; mt++)
#pragma unroll
                for (int nt = 0; nt < NT; nt++) mma16816(acc[mt][nt], a_l[mt], b_h[nt]);
        }
        __syncthreads();
    }

    // ---- epilogue: d0,d1 at (row, col..col+1); d2,d3 at (row+8, ...) ----
#pragma unroll
    for (int mt = 0; mt < MT; mt++) {
#pragma unroll
        for (int nt = 0; nt < NT; nt++) {
            int r0 = brow + wm * TMW + mt * 16 + (lane >> 2);
            int cg = bcol + wn * TNW + nt * 8 + ((lane & 3) << 1);
#pragma unroll
            for (int h = 0; h < 2; h++) {
                int r = r0 + h * 8;
                float v0 = acc[mt][nt][2*h], v1 = acc[mt][nt][2*h+1];
                if (BIAS) { v0 += bias[cg]; v1 += bias[cg + 1]; }
                if (GELU) { v0 = gelu_tanh(v0); v1 = gelu_tanh(v1); }
                if (RES) {
                    float2 rv = *(const float2*)(res + (size_t)r * N + cg);
                    v0 += rv.x; v1 += rv.y;
                }
                if (OUTF32)
                    *(float2*)(C + (size_t)r * N + cg) = make_float2(v0, v1);
                if (OUTBF) {
                    bf16 h0, l0, h1, l1;
                    split2(v0, h0, l0); split2(v1, h1, l1);
                    __nv_bfloat162 hh; hh.x = h0; hh.y = h1;
                    __nv_bfloat162 ll; ll.x = l0; ll.y = l1;
                    *(__nv_bfloat162*)(Ch + (size_t)r * ldbf + cg) = hh;
                    *(__nv_bfloat162*)(Cl + (size_t)r * ldbf + cg) = ll;
                }
            }
        }
    }
    if (OUTBF && ldbf > N) {
        // zero-fill K-pad columns [N, ldbf) for this block's rows
        int pads = (ldbf - N) >> 3;                 // uint4 per row
        for (int i = tid; i < BM * pads; i += 256) {
            int r = brow + i / pads;
            int c = N + (i % pads) * 8;
            uint4 z = make_uint4(0, 0, 0, 0);
            *(uint4*)(Ch + (size_t)r * ldbf + c) = z;
            *(uint4*)(Cl + (size_t)r * ldbf + c) = z;
        }
    }
}

// ---------------- segmented scan ------------------------------------
__global__ void scan_local(const float* __restrict__ k, const float* __restrict__ v,
                           const float* __restrict__ td, float* __restrict__ hloc)
{
    int idx = blockIdx.x * blockDim.x + threadIdx.x;
    int seg = idx / BC;
    int rem = idx - seg * BC;
    int b = rem / CC, c = rem - b * CC;
    float d = expf(-expf(td[c]));
    size_t base = ((size_t)(b * TT + seg * LSEG)) * CC + c;
    float h = 0.f;
#pragma unroll 4
    for (int i = 0; i < LSEG; i++) { h = d * h + k[base] * v[base]; base += CC; }
    hloc[idx] = h;
}

__global__ void scan_combine(const float* __restrict__ hloc, const float* __restrict__ h0,
                             const float* __restrict__ td, float* __restrict__ hin,
                             float* __restrict__ out, long out_size)
{
    int rem = blockIdx.x * blockDim.x + threadIdx.x;
    int c = rem & (CC - 1);
    float e = expf(td[c]);
    float dL = expf(-(float)LSEG * e);
    float h = h0[rem];
#pragma unroll
    for (int s = 0; s < SEG; s++) {
        hin[s * BC + rem] = h;
        h = dL * h + hloc[s * BC + rem];
    }
    if (out_size >= (long)MM * CC + BC)
        out[(size_t)MM * CC + rem] = h;
}

__global__ void scan_apply(const float* __restrict__ k, const float* __restrict__ v,
                           const float* __restrict__ q, const float* __restrict__ td,
                           const float* __restrict__ hin,
                           bf16* __restrict__ yh, bf16* __restrict__ yl)
{
    int idx = blockIdx.x * blockDim.x + threadIdx.x;
    int seg = idx / BC;
    int rem = idx - seg * BC;
    int b = rem / CC, c = rem - b * CC;
    float d = expf(-expf(td[c]));
    float h = hin[seg * BC + rem];
    size_t base = ((size_t)(b * TT + seg * LSEG)) * CC + c;
#pragma unroll 4
    for (int i = 0; i < LSEG; i++) {
        h = d * h + k[base] * v[base];
        float y = h * sigmoid_fast(q[base]);
        bf16 hh, ll; split2(y, hh, ll);
        yh[base] = hh; yl[base] = ll;
        base += CC;
    }
}

// ---------------- launch --------------------------------------------
#define SMEM_MM(BN) (2 * (2 * 128 * 128 + 2 * (BN) * 128))

extern "C" void kernel_launch(void* const* d_in, const int* in_sizes, int n_in,
                              void* d_out, int out_size)
{
    const float* x     = (const float*)d_in[0];
    const float* h0    = (const float*)d_in[1];
    const float* ln1_g = (const float*)d_in[2];
    const float* ln1_b = (const float*)d_in[3];
    const float* tm_g  = (const float*)d_in[4];
    const float* tm_b  = (const float*)d_in[5];
    const float* qu    = (const float*)d_in[6];
    const float* qv    = (const float*)d_in[7];
    const float* ku    = (const float*)d_in[8];
    const float* kvw   = (const float*)d_in[9];
    const float* vu    = (const float*)d_in[10];
    const float* vvw   = (const float*)d_in[11];
    const float* td    = (const float*)d_in[12];
    const float* out_w = (const float*)d_in[13];
    const float* out_b = (const float*)d_in[14];
    const float* ln2_g = (const float*)d_in[15];
    const float* ln2_b = (const float*)d_in[16];
    const float* w1    = (const float*)d_in[17];
    const float* b1    = (const float*)d_in[18];
    const float* w2    = (const float*)d_in[19];
    const float* b2    = (const float*)d_in[20];
    const float* adw   = (const float*)d_in[21];
    const float* adb   = (const float*)d_in[22];
    const float* auw   = (const float*)d_in[23];
    const float* aub   = (const float*)d_in[24];
    float* out = (float*)d_out;

    void* p;
#define SYM(var, sym) cudaGetSymbolAddress(&p, sym); auto* var = (decltype(&sym[0]))p
    SYM(xn,  g_xn);  SYM(q, g_q);  SYM(k, g_k);  SYM(v, g_v);
    SYM(x1,  g_x1);  SYM(x2, g_x2);
    SYM(hlc, g_hloc); SYM(hin, g_hin);
    SYM(mixh, g_mix_h); SYM(mixl, g_mix_l);
    SYM(qrh, g_qr_h); SYM(qrl, g_qr_l);
    SYM(krh, g_kr_h); SYM(krl, g_kr_l);
    SYM(vrh, g_vr_h); SYM(vrl, g_vr_l);
    SYM(ysh, g_ys_h); SYM(ysl, g_ys_l);
    SYM(h2h, g_h2_h); SYM(h2l, g_h2_l);
    SYM(ffh, g_ff_h); SYM(ffl, g_ff_l);
    SYM(x2h, g_x2h);  SYM(x2l, g_x2l);
    SYM(adh, g_ad_h); SYM(adl, g_ad_l);
    SYM(quTh, g_quT_h); SYM(quTl, g_quT_l);
    SYM(kuTh, g_kuT_h); SYM(kuTl, g_kuT_l);
    SYM(vuTh, g_vuT_h); SYM(vuTl, g_vuT_l);
    SYM(qvTh, g_qvT_h); SYM(qvTl, g_qvT_l);
    SYM(kvTh, g_kvT_h); SYM(kvTl, g_kvT_l);
    SYM(vvTh, g_vvT_h); SYM(vvTl, g_vvT_l);
    SYM(owTh, g_owT_h); SYM(owTl, g_owT_l);
    SYM(w1Th, g_w1T_h); SYM(w1Tl, g_w1T_l);
    SYM(w2Th, g_w2T_h); SYM(w2Tl, g_w2T_l);
    SYM(adwTh, g_adwT_h); SYM(adwTl, g_adwT_l);
    SYM(auwTh, g_auwT_h); SYM(auwTl, g_auwT_l);
#undef SYM

    // GEMM variants: <BN, WARPS_M, WARPS_N, BIAS, GELU, RES, OUTF32, OUTBF>
    auto mm_down = mm_bf16<64, 4, 2, false, false, false, false, true >;
    auto mm_up   = mm_bf16<128, 2, 4, false, false, false, true,  false>;
    auto mm_resb = mm_bf16<128, 2, 4, true,  false, true,  true,  false>;
    auto mm_ffn1 = mm_bf16<128, 2, 4, true,  true,  false, false, true >;
    auto mm_ffn2 = mm_bf16<128, 2, 4, true,  false, true,  true,  true >;
    auto mm_adpt = mm_bf16<32, 8, 1, true,  true,  false, false, true >;
    cudaFuncSetAttribute(mm_down, cudaFuncAttributeMaxDynamicSharedMemorySize, SMEM_MM(64));
    cudaFuncSetAttribute(mm_up,   cudaFuncAttributeMaxDynamicSharedMemorySize, SMEM_MM(128));
    cudaFuncSetAttribute(mm_resb, cudaFuncAttributeMaxDynamicSharedMemorySize, SMEM_MM(128));
    cudaFuncSetAttribute(mm_ffn1, cudaFuncAttributeMaxDynamicSharedMemorySize, SMEM_MM(128));
    cudaFuncSetAttribute(mm_ffn2, cudaFuncAttributeMaxDynamicSharedMemorySize, SMEM_MM(128));
    cudaFuncSetAttribute(mm_adpt, cudaFuncAttributeMaxDynamicSharedMemorySize, SMEM_MM(32));

    dim3 tb(32, 8);
    // ---- weight transposes (independent of activations) ----
    transpose_split<<<dim3(RR/32,  CC/32), tb>>>(qu,  CC, RR,  CC,  quTh, quTl);
    transpose_split<<<dim3(RR/32,  CC/32), tb>>>(ku,  CC, RR,  CC,  kuTh, kuTl);
    transpose_split<<<dim3(RR/32,  CC/32), tb>>>(vu,  CC, RR,  CC,  vuTh, vuTl);
    transpose_split<<<dim3(CC/32,  RR/32), tb>>>(qv,  RR, CC,  RR,  qvTh, qvTl);
    transpose_split<<<dim3(CC/32,  RR/32), tb>>>(kvw, RR, CC,  RR,  kvTh, kvTl);
    transpose_split<<<dim3(CC/32,  RR/32), tb>>>(vvw, RR, CC,  RR,  vvTh, vvTl);
    transpose_split<<<dim3(CC/32,  CC/32), tb>>>(out_w, CC, CC, CC, owTh, owTl);
    transpose_split<<<dim3(FFD/32, CC/32), tb>>>(w1,  CC, FFD, CC,  w1Th, w1Tl);
    transpose_split<<<dim3(CC/32,  FFD/32),tb>>>(w2,  FFD, CC, FFD, w2Th, w2Tl);
    transpose_split<<<dim3(ARR/32, CC/32), tb>>>(adw, CC, ARR, CC,  adwTh, adwTl);
    transpose_split<<<dim3(CC/32,  64/32), tb>>>(auw, ARR, CC, 64,  auwTh, auwTl);

    // 1) xn = LN(LN(x, ln1), tm_ln); mix = 0.5*(xn + shift(xn)) split to bf16
    ln_kernel<<<MM, 256>>>(x, ln1_g, ln1_b, tm_g, tm_b, xn, nullptr, nullptr);
    mix_split<<<MM*CC/1024, 256>>>(xn, mixh, mixl);

    // 2) low-rank down-projections (N=64, K=1024)
    mm_down<<<dim3(1, MM/128), 256, SMEM_MM(64)>>>(MM, RR, CC, RR, mixh, mixl, quTh, quTl,
                                                   nullptr, qrh, qrl, nullptr, nullptr);
    mm_down<<<dim3(1, MM/128), 256, SMEM_MM(64)>>>(MM, RR, CC, RR, mixh, mixl, kuTh, kuTl,
                                                   nullptr, krh, krl, nullptr, nullptr);
    mm_down<<<dim3(1, MM/128), 256, SMEM_MM(64)>>>(MM, RR, CC, RR, mixh, mixl, vuTh, vuTl,
                                                   nullptr, vrh, vrl, nullptr, nullptr);

    // 3) up-projections (N=1024, K=64) -> fp32 q,k,v
    mm_up<<<dim3(CC/128, MM/128), 256, SMEM_MM(128)>>>(MM, CC, RR, 0, qrh, qrl, qvTh, qvTl,
                                                       q, nullptr, nullptr, nullptr, nullptr);
    mm_up<<<dim3(CC/128, MM/128), 256, SMEM_MM(128)>>>(MM, CC, RR, 0, krh, krl, kvTh, kvTl,
                                                       k, nullptr, nullptr, nullptr, nullptr);
    mm_up<<<dim3(CC/128, MM/128), 256, SMEM_MM(128)>>>(MM, CC, RR, 0, vrh, vrl, vvTh, vvTl,
                                                       v, nullptr, nullptr, nullptr, nullptr);

    // 4) segmented scan -> ys (bf16 pair)
    scan_local  <<<(SEG*BC)/256, 256>>>(k, v, td, hlc);
    scan_combine<<<BC/256, 256>>>(hlc, h0, td, hin, out, (long)out_size);
    scan_apply  <<<(SEG*BC)/256, 256>>>(k, v, q, td, hin, ysh, ysl);

    // 5) out-proj + bias + residual(x) -> x1 fp32
    mm_resb<<<dim3(CC/128, MM/128), 256, SMEM_MM(128)>>>(MM, CC, CC, 0, ysh, ysl, owTh, owTl,
                                                         x1, nullptr, nullptr, out_b, x);

    // 6) h2 = LN2(x1) -> bf16 pair
    ln_kernel<<<MM, 256>>>(x1, ln2_g, ln2_b, nullptr, nullptr, nullptr, h2h, h2l);

    // 7) FFN
    mm_ffn1<<<dim3(FFD/128, MM/128), 256, SMEM_MM(128)>>>(MM, FFD, CC, FFD, h2h, h2l, w1Th, w1Tl,
                                                          nullptr, ffh, ffl, b1, nullptr);
    mm_ffn2<<<dim3(CC/128, MM/128), 256, SMEM_MM(128)>>>(MM, CC, FFD, CC, ffh, ffl, w2Th, w2Tl,
                                                         x2, x2h, x2l, b2, x1);

    // 8) adapter: down (N=32, K-pad to 64) then up (K=64) with residual x2
    mm_adpt<<<dim3(1, MM/128), 256, SMEM_MM(32)>>>(MM, ARR, CC, 64, x2h, x2l, adwTh, adwTl,
                                                   nullptr, adh, adl, adb, nullptr);
    mm_resb<<<dim3(CC/128, MM/128), 256, SMEM_MM(128)>>>(MM, CC, 64, 0, adh, adl, auwTh, auwTl,
                                                         out, nullptr, nullptr, aub, x2);
}

// round 5
// speedup vs baseline: 4.0786x; 1.2827x over previous
#include <cuda_runtime.h>
#include <cuda_fp16.h>
#include <math.h>
#include <stdint.h>

// ---------------- problem constants (fixed shapes) ----------------
#define BB   8
#define TT   2048
#define CC   1024
#define RR   64
#define ARR  32
#define FFD  4096
#define MM   (BB*TT)        // 16384 rows
#define SEG  16
#define LSEG (TT/SEG)       // 128
#define BC   (BB*CC)        // 8192 channels

typedef __half f16;

// ---------------- scratch (static device globals; no allocs) ------
__device__ __align__(256) float g_xn[MM*CC];
__device__ __align__(256) float g_q [MM*CC];
__device__ __align__(256) float g_k [MM*CC];
__device__ __align__(256) float g_v [MM*CC];
__device__ __align__(256) float g_x1[MM*CC];
__device__ __align__(256) float g_x2[MM*CC];
__device__ __align__(256) float g_hloc[SEG*BC];
__device__ __align__(256) float g_hin [SEG*BC];

// fp16 activation buffers (hi, and lo only where 3-pass consumes them)
__device__ __align__(256) f16 g_mix_h[MM*CC],  g_mix_l[MM*CC];
__device__ __align__(256) f16 g_qr_h[MM*RR],   g_qr_l[MM*RR];
__device__ __align__(256) f16 g_kr_h[MM*RR],   g_kr_l[MM*RR];
__device__ __align__(256) f16 g_vr_h[MM*RR],   g_vr_l[MM*RR];
__device__ __align__(256) f16 g_ys_h[MM*CC];
__device__ __align__(256) f16 g_h2_h[MM*CC];
__device__ __align__(256) f16 g_ff_h[(size_t)MM*FFD];
__device__ __align__(256) f16 g_x2h[MM*CC];
__device__ __align__(256) f16 g_ad_h[MM*64];          // K padded 32->64

// fp16 hi/lo transposed weights  ([N,K] K-major)
__device__ __align__(256) f16 g_quT_h[RR*CC],  g_quT_l[RR*CC];
__device__ __align__(256) f16 g_kuT_h[RR*CC],  g_kuT_l[RR*CC];
__device__ __align__(256) f16 g_vuT_h[RR*CC],  g_vuT_l[RR*CC];
__device__ __align__(256) f16 g_qvT_h[CC*RR],  g_qvT_l[CC*RR];
__device__ __align__(256) f16 g_kvT_h[CC*RR],  g_kvT_l[CC*RR];
__device__ __align__(256) f16 g_vvT_h[CC*RR],  g_vvT_l[CC*RR];
__device__ __align__(256) f16 g_owT_h[CC*CC],  g_owT_l[CC*CC];
__device__ __align__(256) f16 g_w1T_h[(size_t)FFD*CC], g_w1T_l[(size_t)FFD*CC];
__device__ __align__(256) f16 g_w2T_h[(size_t)CC*FFD], g_w2T_l[(size_t)CC*FFD];
__device__ __align__(256) f16 g_adwT_h[ARR*CC],g_adwT_l[ARR*CC];
__device__ __align__(256) f16 g_auwT_h[CC*64], g_auwT_l[CC*64];  // K padded 32->64

// ---------------- PTX helpers ---------------------------------------
__device__ __forceinline__ uint32_t smem_u32(const void* p) {
    uint32_t a;
    asm("{ .reg .u64 t; cvta.to.shared.u64 t, %1; cvt.u32.u64 %0, t; }" : "=r"(a) : "l"(p));
    return a;
}
#define SWZ128(b) ((b) ^ (((b) >> 3) & 0x70))

__device__ __forceinline__ void cp16(uint32_t dst, const void* src) {
    asm volatile("cp.async.cg.shared.global [%0], [%1], 16;" :: "r"(dst), "l"(src));
}
#define CP_COMMIT()  asm volatile("cp.async.commit_group;" ::: "memory")
#define CP_WAIT(n)   asm volatile("cp.async.wait_group %0;" :: "n"(n) : "memory")

__device__ __forceinline__ void ldsm_x4(uint32_t* r, uint32_t addr) {
    asm volatile("ldmatrix.sync.aligned.m8n8.x4.shared.b16 {%0,%1,%2,%3}, [%4];"
                 : "=r"(r[0]), "=r"(r[1]), "=r"(r[2]), "=r"(r[3]) : "r"(addr));
}
__device__ __forceinline__ void mma16816(float* d, const uint32_t* a, const uint32_t* b) {
    asm volatile("mma.sync.aligned.m16n8k16.row.col.f32.f16.f16.f32 "
                 "{%0,%1,%2,%3}, {%4,%5,%6,%7}, {%8,%9}, {%0,%1,%2,%3};"
                 : "+f"(d[0]), "+f"(d[1]), "+f"(d[2]), "+f"(d[3])
                 : "r"(a[0]), "r"(a[1]), "r"(a[2]), "r"(a[3]), "r"(b[0]), "r"(b[1]));
}
__device__ __forceinline__ float tanh_fast(float x) {
    float y;
    asm("tanh.approx.f32 %0, %1;" : "=f"(y) : "f"(x));
    return y;
}

// ---------------- misc helpers --------------------------------------
__device__ __forceinline__ float gelu_tanh(float x) {
    float x3 = x * x * x;
    return 0.5f * x * (1.f + tanh_fast(0.7978845608028654f * (x + 0.044715f * x3)));
}
__device__ __forceinline__ float sigmoid_fast(float x) {
    return 0.5f + 0.5f * tanh_fast(0.5f * x);
}
__device__ __forceinline__ void split2(float x, f16& h, f16& l) {
    h = __float2half_rn(x);
    l = __float2half_rn(x - __half2float(h));
}
__device__ __forceinline__ float block_sum_256(float val, float* sh) {
    int lane = threadIdx.x & 31;
#pragma unroll
    for (int o = 16; o > 0; o >>= 1) val += __shfl_xor_sync(0xffffffffu, val, o);
    if (lane == 0) sh[threadIdx.x >> 5] = val;
    __syncthreads();
    float r = (lane < 8) ? sh[lane] : 0.f;
#pragma unroll
    for (int o = 4; o > 0; o >>= 1) r += __shfl_xor_sync(0xffffffffu, r, o);
    r = __shfl_sync(0xffffffffu, r, 0);
    __syncthreads();
    return r;
}

// ---------------- LayerNorm -----------------------------------------
__global__ void ln_kernel(const float* __restrict__ x,
                          const float* __restrict__ g1, const float* __restrict__ b1,
                          const float* __restrict__ g2, const float* __restrict__ b2,
                          float* __restrict__ out, f16* __restrict__ oh)
{
    __shared__ float sh[8];
    int row = blockIdx.x;
    int tid = threadIdx.x;
    const float* xr = x + (size_t)row * CC;
    float v[4];
#pragma unroll
    for (int i = 0; i < 4; i++) v[i] = xr[tid + i * 256];

#pragma unroll 1
    for (int pass = 0; pass < 2; pass++) {
        const float* gg = pass ? g2 : g1;
        const float* bb = pass ? b2 : b1;
        if (gg == nullptr) break;
        float s = v[0] + v[1] + v[2] + v[3];
        float mean = block_sum_256(s, sh) * (1.f / CC);
        float s2 = 0.f;
#pragma unroll
        for (int i = 0; i < 4; i++) { float d = v[i] - mean; s2 += d * d; }
        float var = block_sum_256(s2, sh) * (1.f / CC);
        float rstd = rsqrtf(var + 1e-5f);
#pragma unroll
        for (int i = 0; i < 4; i++) {
            int idx = tid + i * 256;
            v[i] = (v[i] - mean) * rstd * gg[idx] + bb[idx];
        }
    }
#pragma unroll
    for (int i = 0; i < 4; i++) {
        size_t o = (size_t)row * CC + tid + i * 256;
        if (out) out[o] = v[i];
        if (oh)  oh[o]  = __float2half_rn(v[i]);
    }
}

// ---------------- mix + split ----------------------------------------
__global__ void mix_split(const float* __restrict__ xn,
                          f16* __restrict__ mh, f16* __restrict__ ml)
{
    size_t i = ((size_t)blockIdx.x * 256 + threadIdx.x) * 4;
    int row = (int)(i >> 10);
    int t = row & (TT - 1);
    float4 a = *(const float4*)(xn + i);
    float4 p = make_float4(0.f, 0.f, 0.f, 0.f);
    if (t > 0) p = *(const float4*)(xn + i - CC);
    float m[4] = {0.5f*(a.x+p.x), 0.5f*(a.y+p.y), 0.5f*(a.z+p.z), 0.5f*(a.w+p.w)};
#pragma unroll
    for (int j = 0; j < 4; j++) { f16 h, l; split2(m[j], h, l); mh[i+j] = h; ml[i+j] = l; }
}

// ---------------- weight transpose + split ---------------------------
__global__ void transpose_split(const float* __restrict__ w, int R, int S, int ldout,
                                f16* __restrict__ th, f16* __restrict__ tl)
{
    __shared__ float t[32][33];
    int s0 = blockIdx.x * 32, r0 = blockIdx.y * 32;
#pragma unroll
    for (int i = threadIdx.y; i < 32; i += 8) {
        float v = 0.f;
        if (r0 + i < R) v = w[(size_t)(r0 + i) * S + s0 + threadIdx.x];
        t[i][threadIdx.x] = v;
    }
    __syncthreads();
#pragma unroll
    for (int i = threadIdx.y; i < 32; i += 8) {
        float v = t[threadIdx.x][i];
        size_t o = (size_t)(s0 + i) * ldout + r0 + threadIdx.x;
        f16 h, l; split2(v, h, l);
        th[o] = h; tl[o] = l;
    }
}

// ---------------- HMMA fp16 split GEMM --------------------------------
// D[M,N] = A[M,K] @ B[N,K]^T, fp32 accum.
// PASSES=2: D = Ah*(Bh+Bl)       (A rounded once, B exact-split)
// PASSES=3: D = Ah*Bh + Ah*Bl + Al*Bh
// BM=128, BK=64 halves (SW128 rows), cp.async double buffer.
template<int BN, int WMS, int WNS, int PASSES,
         bool BIAS, bool GELU, bool RES, bool OUTF32, bool OUTH, bool OUTL>
__global__ void __launch_bounds__(256, 1)
mm_h(int M, int N, int K, int ldh,
     const f16* __restrict__ Ah, const f16* __restrict__ Al,
     const f16* __restrict__ Bh, const f16* __restrict__ Bl,
     float* __restrict__ C, f16* __restrict__ Ch, f16* __restrict__ Cl,
     const float* __restrict__ bias, const float* __restrict__ res)
{
    constexpr int BM = 128;
    constexpr int AT = (PASSES == 3) ? 2 : 1;   // A tiles per stage
    constexpr int TMW = BM / WMS;
    constexpr int TNW = BN / WNS;
    constexpr int MT = TMW / 16;
    constexpr int NT = TNW / 8;
    constexpr int A_BYTES = BM * 128;
    constexpr int B_BYTES = BN * 128;
    constexpr int STAGE   = AT * A_BYTES + 2 * B_BYTES;

    extern __shared__ char smem[];
    const uint32_t sb = smem_u32(smem);

    const int tid  = threadIdx.x;
    const int lane = tid & 31;
    const int warp = tid >> 5;
    const int wm   = warp / WNS;
    const int wn   = warp % WNS;
    const int brow = blockIdx.y * BM;
    const int bcol = blockIdx.x * BN;
    const int NK   = K >> 6;

    float acc[MT][NT][4];
#pragma unroll
    for (int i = 0; i < MT; i++)
#pragma unroll
        for (int j = 0; j < NT; j++)
#pragma unroll
            for (int e = 0; e < 4; e++) acc[i][j][e] = 0.f;

    auto load_stage = [&](int kc, int s) {
        uint32_t base = sb + s * STAGE;
#pragma unroll 2
        for (int i = tid; i < BM * 8; i += 256) {
            int r = i >> 3, j = i & 7;
            size_t go = (size_t)(brow + r) * K + (size_t)kc * 64 + j * 8;
            uint32_t sw = SWZ128((uint32_t)(r * 128 + j * 16));
            cp16(base + sw, Ah + go);
            if (PASSES == 3) cp16(base + A_BYTES + sw, Al + go);
        }
#pragma unroll 2
        for (int i = tid; i < BN * 8; i += 256) {
            int r = i >> 3, j = i & 7;
            size_t go = (size_t)(bcol + r) * K + (size_t)kc * 64 + j * 8;
            uint32_t sw = SWZ128((uint32_t)(r * 128 + j * 16));
            cp16(base + AT * A_BYTES + sw, Bh + go);
            cp16(base + AT * A_BYTES + B_BYTES + sw, Bl + go);
        }
        CP_COMMIT();
    };

    load_stage(0, 0);

    for (int kc = 0; kc < NK; kc++) {
        if (kc + 1 < NK) { load_stage(kc + 1, (kc + 1) & 1); CP_WAIT(1); }
        else             { CP_WAIT(0); }
        __syncthreads();

        const uint32_t st = sb + (kc & 1) * STAGE;
#pragma unroll
        for (int ks = 0; ks < 4; ks++) {
            uint32_t a_h[MT][4], a_l[PASSES == 3 ? MT : 1][4];
#pragma unroll
            for (int mt = 0; mt < MT; mt++) {
                int r = wm * TMW + mt * 16 + (lane & 15);
                uint32_t off = SWZ128((uint32_t)(r * 128 + ks * 32 + ((lane >> 4) << 4)));
                ldsm_x4(a_h[mt], st + off);
                if (PASSES == 3) ldsm_x4(a_l[mt], st + A_BYTES + off);
            }
            uint32_t b_h[NT][2], b_l[NT][2];
#pragma unroll
            for (int p = 0; p < NT / 2; p++) {
                int r = wn * TNW + p * 16 + (lane & 7) + ((lane >> 4) << 3);
                uint32_t off = SWZ128((uint32_t)(r * 128 + ks * 32 + (((lane >> 3) & 1) << 4)));
                uint32_t t4[4];
                ldsm_x4(t4, st + AT * A_BYTES + off);
                b_h[2*p][0] = t4[0]; b_h[2*p][1] = t4[1];
                b_h[2*p+1][0] = t4[2]; b_h[2*p+1][1] = t4[3];
                ldsm_x4(t4, st + AT * A_BYTES + B_BYTES + off);
                b_l[2*p][0] = t4[0]; b_l[2*p][1] = t4[1];
                b_l[2*p+1][0] = t4[2]; b_l[2*p+1][1] = t4[3];
            }
#pragma unroll
            for (int mt = 0; mt < MT; mt++)
#pragma unroll
                for (int nt = 0; nt < NT; nt++) mma16816(acc[mt][nt], a_h[mt], b_h[nt]);
#pragma unroll
            for (int mt = 0; mt < MT; mt++)
#pragma unroll
                for (int nt = 0; nt < NT; nt++) mma16816(acc[mt][nt], a_h[mt], b_l[nt]);
            if (PASSES == 3) {
#pragma unroll
                for (int mt = 0; mt < MT; mt++)
#pragma unroll
                    for (int nt = 0; nt < NT; nt++) mma16816(acc[mt][nt], a_l[mt], b_h[nt]);
            }
        }
        __syncthreads();
    }

    // ---- epilogue ----
#pragma unroll
    for (int mt = 0; mt < MT; mt++) {
#pragma unroll
        for (int nt = 0; nt < NT; nt++) {
            int r0 = brow + wm * TMW + mt * 16 + (lane >> 2);
            int cg = bcol + wn * TNW + nt * 8 + ((lane & 3) << 1);
#pragma unroll
            for (int h = 0; h < 2; h++) {
                int r = r0 + h * 8;
                float v0 = acc[mt][nt][2*h], v1 = acc[mt][nt][2*h+1];
                if (BIAS) { v0 += bias[cg]; v1 += bias[cg + 1]; }
                if (GELU) { v0 = gelu_tanh(v0); v1 = gelu_tanh(v1); }
                if (RES) {
                    float2 rv = *(const float2*)(res + (size_t)r * N + cg);
                    v0 += rv.x; v1 += rv.y;
                }
                if (OUTF32)
                    *(float2*)(C + (size_t)r * N + cg) = make_float2(v0, v1);
                if (OUTH) {
                    if (OUTL) {
                        f16 h0, l0, h1, l1;
                        split2(v0, h0, l0); split2(v1, h1, l1);
                        __half2 hh; hh.x = h0; hh.y = h1;
                        __half2 ll; ll.x = l0; ll.y = l1;
                        *(__half2*)(Ch + (size_t)r * ldh + cg) = hh;
                        *(__half2*)(Cl + (size_t)r * ldh + cg) = ll;
                    } else {
                        __half2 hh; hh.x = __float2half_rn(v0); hh.y = __float2half_rn(v1);
                        *(__half2*)(Ch + (size_t)r * ldh + cg) = hh;
                    }
                }
            }
        }
    }
    if (OUTH && ldh > N) {
        int pads = (ldh - N) >> 3;
        for (int i = tid; i < BM * pads; i += 256) {
            int r = brow + i / pads;
            int c = N + (i % pads) * 8;
            uint4 z = make_uint4(0, 0, 0, 0);
            *(uint4*)(Ch + (size_t)r * ldh + c) = z;
            if (OUTL) *(uint4*)(Cl + (size_t)r * ldh + c) = z;
        }
    }
}

// ---------------- segmented scan --------------------------------------
__global__ void scan_local(const float* __restrict__ k, const float* __restrict__ v,
                           const float* __restrict__ td, float* __restrict__ hloc)
{
    int idx = blockIdx.x * blockDim.x + threadIdx.x;
    int seg = idx / BC;
    int rem = idx - seg * BC;
    int b = rem / CC, c = rem - b * CC;
    float d = expf(-expf(td[c]));
    size_t base = ((size_t)(b * TT + seg * LSEG)) * CC + c;
    float h = 0.f;
#pragma unroll 4
    for (int i = 0; i < LSEG; i++) { h = d * h + k[base] * v[base]; base += CC; }
    hloc[idx] = h;
}

__global__ void scan_combine(const float* __restrict__ hloc, const float* __restrict__ h0,
                             const float* __restrict__ td, float* __restrict__ hin,
                             float* __restrict__ out, long out_size)
{
    int rem = blockIdx.x * blockDim.x + threadIdx.x;
    int c = rem & (CC - 1);
    float e = expf(td[c]);
    float dL = expf(-(float)LSEG * e);
    float h = h0[rem];
#pragma unroll
    for (int s = 0; s < SEG; s++) {
        hin[s * BC + rem] = h;
        h = dL * h + hloc[s * BC + rem];
    }
    if (out_size >= (long)MM * CC + BC)
        out[(size_t)MM * CC + rem] = h;
}

__global__ void scan_apply(const float* __restrict__ k, const float* __restrict__ v,
                           const float* __restrict__ q, const float* __restrict__ td,
                           const float* __restrict__ hin, f16* __restrict__ yh)
{
    int idx = blockIdx.x * blockDim.x + threadIdx.x;
    int seg = idx / BC;
    int rem = idx - seg * BC;
    int b = rem / CC, c = rem - b * CC;
    float d = expf(-expf(td[c]));
    float h = hin[seg * BC + rem];
    size_t base = ((size_t)(b * TT + seg * LSEG)) * CC + c;
#pragma unroll 4
    for (int i = 0; i < LSEG; i++) {
        h = d * h + k[base] * v[base];
        yh[base] = __float2half_rn(h * sigmoid_fast(q[base]));
        base += CC;
    }
}

// ---------------- launch ----------------------------------------------
#define SM_P3(BN) (2 * ((2 * 128 + 2 * (BN)) * 128))
#define SM_P2(BN) (2 * ((128 + 2 * (BN)) * 128))

extern "C" void kernel_launch(void* const* d_in, const int* in_sizes, int n_in,
                              void* d_out, int out_size)
{
    const float* x     = (const float*)d_in[0];
    const float* h0    = (const float*)d_in[1];
    const float* ln1_g = (const float*)d_in[2];
    const float* ln1_b = (const float*)d_in[3];
    const float* tm_g  = (const float*)d_in[4];
    const float* tm_b  = (const float*)d_in[5];
    const float* qu    = (const float*)d_in[6];
    const float* qv    = (const float*)d_in[7];
    const float* ku    = (const float*)d_in[8];
    const float* kvw   = (const float*)d_in[9];
    const float* vu    = (const float*)d_in[10];
    const float* vvw   = (const float*)d_in[11];
    const float* td    = (const float*)d_in[12];
    const float* out_w = (const float*)d_in[13];
    const float* out_b = (const float*)d_in[14];
    const float* ln2_g = (const float*)d_in[15];
    const float* ln2_b = (const float*)d_in[16];
    const float* w1    = (const float*)d_in[17];
    const float* b1    = (const float*)d_in[18];
    const float* w2    = (const float*)d_in[19];
    const float* b2    = (const float*)d_in[20];
    const float* adw   = (const float*)d_in[21];
    const float* adb   = (const float*)d_in[22];
    const float* auw   = (const float*)d_in[23];
    const float* aub   = (const float*)d_in[24];
    float* out = (float*)d_out;

    void* p;
#define SYM(var, sym) cudaGetSymbolAddress(&p, sym); auto* var = (decltype(&sym[0]))p
    SYM(xn,  g_xn);  SYM(q, g_q);  SYM(k, g_k);  SYM(v, g_v);
    SYM(x1,  g_x1);  SYM(x2, g_x2);
    SYM(hlc, g_hloc); SYM(hin, g_hin);
    SYM(mixh, g_mix_h); SYM(mixl, g_mix_l);
    SYM(qrh, g_qr_h); SYM(qrl, g_qr_l);
    SYM(krh, g_kr_h); SYM(krl, g_kr_l);
    SYM(vrh, g_vr_h); SYM(vrl, g_vr_l);
    SYM(ysh, g_ys_h);
    SYM(h2h, g_h2_h);
    SYM(ffh, g_ff_h);
    SYM(x2h, g_x2h);
    SYM(adh, g_ad_h);
    SYM(quTh, g_quT_h); SYM(quTl, g_quT_l);
    SYM(kuTh, g_kuT_h); SYM(kuTl, g_kuT_l);
    SYM(vuTh, g_vuT_h); SYM(vuTl, g_vuT_l);
    SYM(qvTh, g_qvT_h); SYM(qvTl, g_qvT_l);
    SYM(kvTh, g_kvT_h); SYM(kvTl, g_kvT_l);
    SYM(vvTh, g_vvT_h); SYM(vvTl, g_vvT_l);
    SYM(owTh, g_owT_h); SYM(owTl, g_owT_l);
    SYM(w1Th, g_w1T_h); SYM(w1Tl, g_w1T_l);
    SYM(w2Th, g_w2T_h); SYM(w2Tl, g_w2T_l);
    SYM(adwTh, g_adwT_h); SYM(adwTl, g_adwT_l);
    SYM(auwTh, g_auwT_h); SYM(auwTl, g_auwT_l);
#undef SYM

    // variants: <BN, WM, WN, PASSES, BIAS, GELU, RES, OUTF32, OUTH, OUTL>
    auto mm_down = mm_h<64, 4, 2, 3, false, false, false, false, true,  true >;
    auto mm_up   = mm_h<128, 2, 4, 3, false, false, false, true,  false, false>;
    auto mm_oprj = mm_h<128, 2, 4, 2, true,  false, true,  true,  false, false>;
    auto mm_ffn1 = mm_h<128, 2, 4, 2, true,  true,  false, false, true,  false>;
    auto mm_ffn2 = mm_h<128, 2, 4, 2, true,  false, true,  true,  true,  false>;
    auto mm_add  = mm_h<32, 8, 1, 2, true,  true,  false, false, true,  false>;
    auto mm_adu  = mm_h<128, 2, 4, 2, true,  false, true,  true,  false, false>;
    cudaFuncSetAttribute(mm_down, cudaFuncAttributeMaxDynamicSharedMemorySize, SM_P3(64));
    cudaFuncSetAttribute(mm_up,   cudaFuncAttributeMaxDynamicSharedMemorySize, SM_P3(128));
    cudaFuncSetAttribute(mm_oprj, cudaFuncAttributeMaxDynamicSharedMemorySize, SM_P2(128));
    cudaFuncSetAttribute(mm_ffn1, cudaFuncAttributeMaxDynamicSharedMemorySize, SM_P2(128));
    cudaFuncSetAttribute(mm_ffn2, cudaFuncAttributeMaxDynamicSharedMemorySize, SM_P2(128));
    cudaFuncSetAttribute(mm_add,  cudaFuncAttributeMaxDynamicSharedMemorySize, SM_P2(32));
    cudaFuncSetAttribute(mm_adu,  cudaFuncAttributeMaxDynamicSharedMemorySize, SM_P2(128));

    dim3 tb(32, 8);
    // ---- weight transposes ----
    transpose_split<<<dim3(RR/32,  CC/32), tb>>>(qu,  CC, RR,  CC,  quTh, quTl);
    transpose_split<<<dim3(RR/32,  CC/32), tb>>>(ku,  CC, RR,  CC,  kuTh, kuTl);
    transpose_split<<<dim3(RR/32,  CC/32), tb>>>(vu,  CC, RR,  CC,  vuTh, vuTl);
    transpose_split<<<dim3(CC/32,  RR/32), tb>>>(qv,  RR, CC,  RR,  qvTh, qvTl);
    transpose_split<<<dim3(CC/32,  RR/32), tb>>>(kvw, RR, CC,  RR,  kvTh, kvTl);
    transpose_split<<<dim3(CC/32,  RR/32), tb>>>(vvw, RR, CC,  RR,  vvTh, vvTl);
    transpose_split<<<dim3(CC/32,  CC/32), tb>>>(out_w, CC, CC, CC, owTh, owTl);
    transpose_split<<<dim3(FFD/32, CC/32), tb>>>(w1,  CC, FFD, CC,  w1Th, w1Tl);
    transpose_split<<<dim3(CC/32,  FFD/32),tb>>>(w2,  FFD, CC, FFD, w2Th, w2Tl);
    transpose_split<<<dim3(ARR/32, CC/32), tb>>>(adw, CC, ARR, CC,  adwTh, adwTl);
    transpose_split<<<dim3(CC/32,  64/32), tb>>>(auw, ARR, CC, 64,  auwTh, auwTl);

    // 1) xn = LN(LN(x)); mix = 0.5*(xn + shift(xn)) split to fp16 pair
    ln_kernel<<<MM, 256>>>(x, ln1_g, ln1_b, tm_g, tm_b, xn, nullptr);
    mix_split<<<MM*CC/1024, 256>>>(xn, mixh, mixl);

    // 2) low-rank down-projections (N=64, K=1024), 3-pass, out fp16 pair
    mm_down<<<dim3(1, MM/128), 256, SM_P3(64)>>>(MM, RR, CC, RR, mixh, mixl, quTh, quTl,
                                                 nullptr, qrh, qrl, nullptr, nullptr);
    mm_down<<<dim3(1, MM/128), 256, SM_P3(64)>>>(MM, RR, CC, RR, mixh, mixl, kuTh, kuTl,
                                                 nullptr, krh, krl, nullptr, nullptr);
    mm_down<<<dim3(1, MM/128), 256, SM_P3(64)>>>(MM, RR, CC, RR, mixh, mixl, vuTh, vuTl,
                                                 nullptr, vrh, vrl, nullptr, nullptr);

    // 3) up-projections (N=1024, K=64), 3-pass, out fp32
    mm_up<<<dim3(CC/128, MM/128), 256, SM_P3(128)>>>(MM, CC, RR, 0, qrh, qrl, qvTh, qvTl,
                                                     q, nullptr, nullptr, nullptr, nullptr);
    mm_up<<<dim3(CC/128, MM/128), 256, SM_P3(128)>>>(MM, CC, RR, 0, krh, krl, kvTh, kvTl,
                                                     k, nullptr, nullptr, nullptr, nullptr);
    mm_up<<<dim3(CC/128, MM/128), 256, SM_P3(128)>>>(MM, CC, RR, 0, vrh, vrl, vvTh, vvTl,
                                                     v, nullptr, nullptr, nullptr, nullptr);

    // 4) segmented scan -> ys fp16
    scan_local  <<<(SEG*BC)/256, 256>>>(k, v, td, hlc);
    scan_combine<<<BC/256, 256>>>(hlc, h0, td, hin, out, (long)out_size);
    scan_apply  <<<(SEG*BC)/256, 256>>>(k, v, q, td, hin, ysh);

    // 5) out-proj (2-pass) + bias + residual(x) -> x1 fp32
    mm_oprj<<<dim3(CC/128, MM/128), 256, SM_P2(128)>>>(MM, CC, CC, 0, ysh, nullptr, owTh, owTl,
                                                       x1, nullptr, nullptr, out_b, x);

    // 6) h2 = LN2(x1) -> fp16 hi
    ln_kernel<<<MM, 256>>>(x1, ln2_g, ln2_b, nullptr, nullptr, nullptr, h2h);

    // 7) FFN (2-pass)
    mm_ffn1<<<dim3(FFD/128, MM/128), 256, SM_P2(128)>>>(MM, FFD, CC, FFD, h2h, nullptr,
                                                        w1Th, w1Tl, nullptr, ffh, nullptr,
                                                        b1, nullptr);
    mm_ffn2<<<dim3(CC/128, MM/128), 256, SM_P2(128)>>>(MM, CC, FFD, CC, ffh, nullptr,
                                                       w2Th, w2Tl, x2, x2h, nullptr,
                                                       b2, x1);

    // 8) adapter (2-pass): down (N=32, K-pad out to 64) then up (K=64) + res
    mm_add<<<dim3(1, MM/128), 256, SM_P2(32)>>>(MM, ARR, CC, 64, x2h, nullptr, adwTh, adwTl,
                                                nullptr, adh, nullptr, adb, nullptr);
    mm_adu<<<dim3(CC/128, MM/128), 256, SM_P2(128)>>>(MM, CC, 64, 0, adh, nullptr,
                                                      auwTh, auwTl, out, nullptr, nullptr,
                                                      aub, x2);
}

// round 6
// speedup vs baseline: 5.8387x; 1.4316x over previous
#include <cuda_runtime.h>
#include <cuda_fp16.h>
#include <math.h>
#include <stdint.h>

// ---------------- problem constants (fixed shapes) ----------------
#define BB   8
#define TT   2048
#define CC   1024
#define RR   64
#define ARR  32
#define FFD  4096
#define MM   (BB*TT)        // 16384 rows
#define SEG  16
#define LSEG (TT/SEG)       // 128
#define BC   (BB*CC)        // 8192 channels

typedef __half f16;

// ---------------- scratch (static device globals; no allocs) ------
__device__ __align__(256) float g_xn[MM*CC];
__device__ __align__(256) float g_q [MM*CC];
__device__ __align__(256) float g_k [MM*CC];
__device__ __align__(256) float g_v [MM*CC];
__device__ __align__(256) float g_x1[MM*CC];
__device__ __align__(256) float g_x2[MM*CC];
__device__ __align__(256) float g_hloc[SEG*BC];
__device__ __align__(256) float g_hin [SEG*BC];

// fp16 activation buffers
__device__ __align__(256) f16 g_mix_h[MM*CC],  g_mix_l[MM*CC];
__device__ __align__(256) f16 g_qr_h[MM*RR],   g_qr_l[MM*RR];
__device__ __align__(256) f16 g_kr_h[MM*RR],   g_kr_l[MM*RR];
__device__ __align__(256) f16 g_vr_h[MM*RR],   g_vr_l[MM*RR];
__device__ __align__(256) f16 g_ys_h[MM*CC];
__device__ __align__(256) f16 g_h2_h[MM*CC];
__device__ __align__(256) f16 g_ff_h[(size_t)MM*FFD];
__device__ __align__(256) f16 g_x2h[MM*CC];
__device__ __align__(256) f16 g_ad_h[MM*64];          // K padded 32->64

// fp16 transposed weights ([N,K] K-major); lo-half only where 2/3-pass needs it
__device__ __align__(256) f16 g_quT_h[RR*CC],  g_quT_l[RR*CC];
__device__ __align__(256) f16 g_kuT_h[RR*CC],  g_kuT_l[RR*CC];
__device__ __align__(256) f16 g_vuT_h[RR*CC],  g_vuT_l[RR*CC];
__device__ __align__(256) f16 g_qvT_h[CC*RR],  g_qvT_l[CC*RR];
__device__ __align__(256) f16 g_kvT_h[CC*RR],  g_kvT_l[CC*RR];
__device__ __align__(256) f16 g_vvT_h[CC*RR],  g_vvT_l[CC*RR];
__device__ __align__(256) f16 g_owT_h[CC*CC];
__device__ __align__(256) f16 g_w1T_h[(size_t)FFD*CC];
__device__ __align__(256) f16 g_w2T_h[(size_t)CC*FFD];
__device__ __align__(256) f16 g_adwT_h[ARR*CC],g_adwT_l[ARR*CC];
__device__ __align__(256) f16 g_auwT_h[CC*64];        // K padded 32->64

// ---------------- PTX helpers ---------------------------------------
__device__ __forceinline__ uint32_t smem_u32(const void* p) {
    uint32_t a;
    asm("{ .reg .u64 t; cvta.to.shared.u64 t, %1; cvt.u32.u64 %0, t; }" : "=r"(a) : "l"(p));
    return a;
}
#define SWZ128(b) ((b) ^ (((b) >> 3) & 0x70))

__device__ __forceinline__ void cp16(uint32_t dst, const void* src) {
    asm volatile("cp.async.cg.shared.global [%0], [%1], 16;" :: "r"(dst), "l"(src));
}
#define CP_COMMIT()  asm volatile("cp.async.commit_group;" ::: "memory")
#define CP_WAIT(n)   asm volatile("cp.async.wait_group %0;" :: "n"(n) : "memory")

__device__ __forceinline__ void ldsm_x4(uint32_t* r, uint32_t addr) {
    asm volatile("ldmatrix.sync.aligned.m8n8.x4.shared.b16 {%0,%1,%2,%3}, [%4];"
                 : "=r"(r[0]), "=r"(r[1]), "=r"(r[2]), "=r"(r[3]) : "r"(addr));
}
__device__ __forceinline__ void mma16816(float* d, const uint32_t* a, const uint32_t* b) {
    asm volatile("mma.sync.aligned.m16n8k16.row.col.f32.f16.f16.f32 "
                 "{%0,%1,%2,%3}, {%4,%5,%6,%7}, {%8,%9}, {%0,%1,%2,%3};"
                 : "+f"(d[0]), "+f"(d[1]), "+f"(d[2]), "+f"(d[3])
                 : "r"(a[0]), "r"(a[1]), "r"(a[2]), "r"(a[3]), "r"(b[0]), "r"(b[1]));
}
__device__ __forceinline__ float tanh_fast(float x) {
    float y;
    asm("tanh.approx.f32 %0, %1;" : "=f"(y) : "f"(x));
    return y;
}

// ---------------- misc helpers --------------------------------------
__device__ __forceinline__ float gelu_tanh(float x) {
    float x3 = x * x * x;
    return 0.5f * x * (1.f + tanh_fast(0.7978845608028654f * (x + 0.044715f * x3)));
}
__device__ __forceinline__ float sigmoid_fast(float x) {
    return 0.5f + 0.5f * tanh_fast(0.5f * x);
}
__device__ __forceinline__ void split2(float x, f16& h, f16& l) {
    h = __float2half_rn(x);
    l = __float2half_rn(x - __half2float(h));
}
__device__ __forceinline__ float block_sum_256(float val, float* sh) {
    int lane = threadIdx.x & 31;
#pragma unroll
    for (int o = 16; o > 0; o >>= 1) val += __shfl_xor_sync(0xffffffffu, val, o);
    if (lane == 0) sh[threadIdx.x >> 5] = val;
    __syncthreads();
    float r = (lane < 8) ? sh[lane] : 0.f;
#pragma unroll
    for (int o = 4; o > 0; o >>= 1) r += __shfl_xor_sync(0xffffffffu, r, o);
    r = __shfl_sync(0xffffffffu, r, 0);
    __syncthreads();
    return r;
}

// ---------------- LayerNorm -----------------------------------------
__global__ void ln_kernel(const float* __restrict__ x,
                          const float* __restrict__ g1, const float* __restrict__ b1,
                          const float* __restrict__ g2, const float* __restrict__ b2,
                          float* __restrict__ out, f16* __restrict__ oh)
{
    __shared__ float sh[8];
    int row = blockIdx.x;
    int tid = threadIdx.x;
    const float* xr = x + (size_t)row * CC;
    float v[4];
#pragma unroll
    for (int i = 0; i < 4; i++) v[i] = xr[tid + i * 256];

#pragma unroll 1
    for (int pass = 0; pass < 2; pass++) {
        const float* gg = pass ? g2 : g1;
        const float* bb = pass ? b2 : b1;
        if (gg == nullptr) break;
        float s = v[0] + v[1] + v[2] + v[3];
        float mean = block_sum_256(s, sh) * (1.f / CC);
        float s2 = 0.f;
#pragma unroll
        for (int i = 0; i < 4; i++) { float d = v[i] - mean; s2 += d * d; }
        float var = block_sum_256(s2, sh) * (1.f / CC);
        float rstd = rsqrtf(var + 1e-5f);
#pragma unroll
        for (int i = 0; i < 4; i++) {
            int idx = tid + i * 256;
            v[i] = (v[i] - mean) * rstd * gg[idx] + bb[idx];
        }
    }
#pragma unroll
    for (int i = 0; i < 4; i++) {
        size_t o = (size_t)row * CC + tid + i * 256;
        if (out) out[o] = v[i];
        if (oh)  oh[o]  = __float2half_rn(v[i]);
    }
}

// ---------------- mix + split ----------------------------------------
__global__ void mix_split(const float* __restrict__ xn,
                          f16* __restrict__ mh, f16* __restrict__ ml)
{
    size_t i = ((size_t)blockIdx.x * 256 + threadIdx.x) * 4;
    int row = (int)(i >> 10);
    int t = row & (TT - 1);
    float4 a = *(const float4*)(xn + i);
    float4 p = make_float4(0.f, 0.f, 0.f, 0.f);
    if (t > 0) p = *(const float4*)(xn + i - CC);
    float m[4] = {0.5f*(a.x+p.x), 0.5f*(a.y+p.y), 0.5f*(a.z+p.z), 0.5f*(a.w+p.w)};
#pragma unroll
    for (int j = 0; j < 4; j++) { f16 h, l; split2(m[j], h, l); mh[i+j] = h; ml[i+j] = l; }
}

// ---------------- weight transpose + split ---------------------------
__global__ void transpose_split(const float* __restrict__ w, int R, int S, int ldout,
                                f16* __restrict__ th, f16* __restrict__ tl)
{
    __shared__ float t[32][33];
    int s0 = blockIdx.x * 32, r0 = blockIdx.y * 32;
#pragma unroll
    for (int i = threadIdx.y; i < 32; i += 8) {
        float v = 0.f;
        if (r0 + i < R) v = w[(size_t)(r0 + i) * S + s0 + threadIdx.x];
        t[i][threadIdx.x] = v;
    }
    __syncthreads();
#pragma unroll
    for (int i = threadIdx.y; i < 32; i += 8) {
        float v = t[threadIdx.x][i];
        size_t o = (size_t)(s0 + i) * ldout + r0 + threadIdx.x;
        f16 h, l; split2(v, h, l);
        th[o] = h;
        if (tl) tl[o] = l;
    }
}

// ---------------- HMMA fp16 split GEMM --------------------------------
// D[M,N] = A[M,K] @ B[N,K]^T, fp32 accum.
// PASSES=1: D = Ah*Bh
// PASSES=2: D = Ah*(Bh+Bl)     (A rounded once, B exact-split)
// PASSES=3: D = Ah*Bh + Ah*Bl + Al*Bh
// BM=128, BK=64 halves (SW128 rows), cp.async double buffer.
template<int BN, int WMS, int WNS, int PASSES,
         bool BIAS, bool GELU, bool RES, bool OUTF32, bool OUTH, bool OUTL>
__global__ void __launch_bounds__(256, 1)
mm_h(int M, int N, int K, int ldh,
     const f16* __restrict__ Ah, const f16* __restrict__ Al,
     const f16* __restrict__ Bh, const f16* __restrict__ Bl,
     float* __restrict__ C, f16* __restrict__ Ch, f16* __restrict__ Cl,
     const float* __restrict__ bias, const float* __restrict__ res)
{
    constexpr int BM = 128;
    constexpr int AT = (PASSES == 3) ? 2 : 1;   // A tiles per stage
    constexpr int BT = (PASSES >= 2) ? 2 : 1;   // B tiles per stage
    constexpr int TMW = BM / WMS;
    constexpr int TNW = BN / WNS;
    constexpr int MT = TMW / 16;
    constexpr int NT = TNW / 8;
    constexpr int A_BYTES = BM * 128;
    constexpr int B_BYTES = BN * 128;
    constexpr int STAGE   = AT * A_BYTES + BT * B_BYTES;

    extern __shared__ char smem[];
    const uint32_t sb = smem_u32(smem);

    const int tid  = threadIdx.x;
    const int lane = tid & 31;
    const int warp = tid >> 5;
    const int wm   = warp / WNS;
    const int wn   = warp % WNS;
    const int brow = blockIdx.y * BM;
    const int bcol = blockIdx.x * BN;
    const int NK   = K >> 6;

    float acc[MT][NT][4];
#pragma unroll
    for (int i = 0; i < MT; i++)
#pragma unroll
        for (int j = 0; j < NT; j++)
#pragma unroll
            for (int e = 0; e < 4; e++) acc[i][j][e] = 0.f;

    auto load_stage = [&](int kc, int s) {
        uint32_t base = sb + s * STAGE;
#pragma unroll 2
        for (int i = tid; i < BM * 8; i += 256) {
            int r = i >> 3, j = i & 7;
            size_t go = (size_t)(brow + r) * K + (size_t)kc * 64 + j * 8;
            uint32_t sw = SWZ128((uint32_t)(r * 128 + j * 16));
            cp16(base + sw, Ah + go);
            if (PASSES == 3) cp16(base + A_BYTES + sw, Al + go);
        }
#pragma unroll 2
        for (int i = tid; i < BN * 8; i += 256) {
            int r = i >> 3, j = i & 7;
            size_t go = (size_t)(bcol + r) * K + (size_t)kc * 64 + j * 8;
            uint32_t sw = SWZ128((uint32_t)(r * 128 + j * 16));
            cp16(base + AT * A_BYTES + sw, Bh + go);
            if (PASSES >= 2) cp16(base + AT * A_BYTES + B_BYTES + sw, Bl + go);
        }
        CP_COMMIT();
    };

    load_stage(0, 0);

    for (int kc = 0; kc < NK; kc++) {
        if (kc + 1 < NK) { load_stage(kc + 1, (kc + 1) & 1); CP_WAIT(1); }
        else             { CP_WAIT(0); }
        __syncthreads();

        const uint32_t st = sb + (kc & 1) * STAGE;
#pragma unroll
        for (int ks = 0; ks < 4; ks++) {
            uint32_t a_h[MT][4], a_l[PASSES == 3 ? MT : 1][4];
#pragma unroll
            for (int mt = 0; mt < MT; mt++) {
                int r = wm * TMW + mt * 16 + (lane & 15);
                uint32_t off = SWZ128((uint32_t)(r * 128 + ks * 32 + ((lane >> 4) << 4)));
                ldsm_x4(a_h[mt], st + off);
                if (PASSES == 3) ldsm_x4(a_l[mt], st + A_BYTES + off);
            }
            uint32_t b_h[NT][2], b_l[PASSES >= 2 ? NT : 1][2];
#pragma unroll
            for (int p = 0; p < NT / 2; p++) {
                int r = wn * TNW + p * 16 + (lane & 7) + ((lane >> 4) << 3);
                uint32_t off = SWZ128((uint32_t)(r * 128 + ks * 32 + (((lane >> 3) & 1) << 4)));
                uint32_t t4[4];
                ldsm_x4(t4, st + AT * A_BYTES + off);
                b_h[2*p][0] = t4[0]; b_h[2*p][1] = t4[1];
                b_h[2*p+1][0] = t4[2]; b_h[2*p+1][1] = t4[3];
                if (PASSES >= 2) {
                    ldsm_x4(t4, st + AT * A_BYTES + B_BYTES + off);
                    b_l[2*p][0] = t4[0]; b_l[2*p][1] = t4[1];
                    b_l[2*p+1][0] = t4[2]; b_l[2*p+1][1] = t4[3];
                }
            }
#pragma unroll
            for (int mt = 0; mt < MT; mt++)
#pragma unroll
                for (int nt = 0; nt < NT; nt++) mma16816(acc[mt][nt], a_h[mt], b_h[nt]);
            if (PASSES >= 2) {
#pragma unroll
                for (int mt = 0; mt < MT; mt++)
#pragma unroll
                    for (int nt = 0; nt < NT; nt++) mma16816(acc[mt][nt], a_h[mt], b_l[nt]);
            }
            if (PASSES == 3) {
#pragma unroll
                for (int mt = 0; mt < MT; mt++)
#pragma unroll
                    for (int nt = 0; nt < NT; nt++) mma16816(acc[mt][nt], a_l[mt], b_h[nt]);
            }
        }
        __syncthreads();
    }

    // ---- epilogue ----
#pragma unroll
    for (int mt = 0; mt < MT; mt++) {
#pragma unroll
        for (int nt = 0; nt < NT; nt++) {
            int r0 = brow + wm * TMW + mt * 16 + (lane >> 2);
            int cg = bcol + wn * TNW + nt * 8 + ((lane & 3) << 1);
#pragma unroll
            for (int h = 0; h < 2; h++) {
                int r = r0 + h * 8;
                float v0 = acc[mt][nt][2*h], v1 = acc[mt][nt][2*h+1];
                if (BIAS) { v0 += bias[cg]; v1 += bias[cg + 1]; }
                if (GELU) { v0 = gelu_tanh(v0); v1 = gelu_tanh(v1); }
                if (RES) {
                    float2 rv = *(const float2*)(res + (size_t)r * N + cg);
                    v0 += rv.x; v1 += rv.y;
                }
                if (OUTF32)
                    *(float2*)(C + (size_t)r * N + cg) = make_float2(v0, v1);
                if (OUTH) {
                    if (OUTL) {
                        f16 h0, l0, h1, l1;
                        split2(v0, h0, l0); split2(v1, h1, l1);
                        __half2 hh; hh.x = h0; hh.y = h1;
                        __half2 ll; ll.x = l0; ll.y = l1;
                        *(__half2*)(Ch + (size_t)r * ldh + cg) = hh;
                        *(__half2*)(Cl + (size_t)r * ldh + cg) = ll;
                    } else {
                        __half2 hh; hh.x = __float2half_rn(v0); hh.y = __float2half_rn(v1);
                        *(__half2*)(Ch + (size_t)r * ldh + cg) = hh;
                    }
                }
            }
        }
    }
    if (OUTH && ldh > N) {
        int pads = (ldh - N) >> 3;
        for (int i = tid; i < BM * pads; i += 256) {
            int r = brow + i / pads;
            int c = N + (i % pads) * 8;
            uint4 z = make_uint4(0, 0, 0, 0);
            *(uint4*)(Ch + (size_t)r * ldh + c) = z;
            if (OUTL) *(uint4*)(Cl + (size_t)r * ldh + c) = z;
        }
    }
}

// ---------------- segmented scan --------------------------------------
__global__ void scan_local(const float* __restrict__ k, const float* __restrict__ v,
                           const float* __restrict__ td, float* __restrict__ hloc)
{
    int idx = blockIdx.x * blockDim.x + threadIdx.x;
    int seg = idx / BC;
    int rem = idx - seg * BC;
    int b = rem / CC, c = rem - b * CC;
    float d = expf(-expf(td[c]));
    size_t base = ((size_t)(b * TT + seg * LSEG)) * CC + c;
    float h = 0.f;
#pragma unroll 4
    for (int i = 0; i < LSEG; i++) { h = d * h + k[base] * v[base]; base += CC; }
    hloc[idx] = h;
}

__global__ void scan_combine(const float* __restrict__ hloc, const float* __restrict__ h0,
                             const float* __restrict__ td, float* __restrict__ hin,
                             float* __restrict__ out, long out_size)
{
    int rem = blockIdx.x * blockDim.x + threadIdx.x;
    int c = rem & (CC - 1);
    float e = expf(td[c]);
    float dL = expf(-(float)LSEG * e);
    float h = h0[rem];
#pragma unroll
    for (int s = 0; s < SEG; s++) {
        hin[s * BC + rem] = h;
        h = dL * h + hloc[s * BC + rem];
    }
    if (out_size >= (long)MM * CC + BC)
        out[(size_t)MM * CC + rem] = h;
}

__global__ void scan_apply(const float* __restrict__ k, const float* __restrict__ v,
                           const float* __restrict__ q, const float* __restrict__ td,
                           const float* __restrict__ hin, f16* __restrict__ yh)
{
    int idx = blockIdx.x * blockDim.x + threadIdx.x;
    int seg = idx / BC;
    int rem = idx - seg * BC;
    int b = rem / CC, c = rem - b * CC;
    float d = expf(-expf(td[c]));
    float h = hin[seg * BC + rem];
    size_t base = ((size_t)(b * TT + seg * LSEG)) * CC + c;
#pragma unroll 4
    for (int i = 0; i < LSEG; i++) {
        h = d * h + k[base] * v[base];
        yh[base] = __float2half_rn(h * sigmoid_fast(q[base]));
        base += CC;
    }
}

// ---------------- launch ----------------------------------------------
#define SM_P3(BN) (2 * ((2 * 128 + 2 * (BN)) * 128))
#define SM_P2(BN) (2 * ((128 + 2 * (BN)) * 128))
#define SM_P1(BN) (2 * ((128 + (BN)) * 128))

extern "C" void kernel_launch(void* const* d_in, const int* in_sizes, int n_in,
                              void* d_out, int out_size)
{
    const float* x     = (const float*)d_in[0];
    const float* h0    = (const float*)d_in[1];
    const float* ln1_g = (const float*)d_in[2];
    const float* ln1_b = (const float*)d_in[3];
    const float* tm_g  = (const float*)d_in[4];
    const float* tm_b  = (const float*)d_in[5];
    const float* qu    = (const float*)d_in[6];
    const float* qv    = (const float*)d_in[7];
    const float* ku    = (const float*)d_in[8];
    const float* kvw   = (const float*)d_in[9];
    const float* vu    = (const float*)d_in[10];
    const float* vvw   = (const float*)d_in[11];
    const float* td    = (const float*)d_in[12];
    const float* out_w = (const float*)d_in[13];
    const float* out_b = (const float*)d_in[14];
    const float* ln2_g = (const float*)d_in[15];
    const float* ln2_b = (const float*)d_in[16];
    const float* w1    = (const float*)d_in[17];
    const float* b1    = (const float*)d_in[18];
    const float* w2    = (const float*)d_in[19];
    const float* b2    = (const float*)d_in[20];
    const float* adw   = (const float*)d_in[21];
    const float* adb   = (const float*)d_in[22];
    const float* auw   = (const float*)d_in[23];
    const float* aub   = (const float*)d_in[24];
    float* out = (float*)d_out;

    void* p;
#define SYM(var, sym) cudaGetSymbolAddress(&p, sym); auto* var = (decltype(&sym[0]))p
    SYM(xn,  g_xn);  SYM(q, g_q);  SYM(k, g_k);  SYM(v, g_v);
    SYM(x1,  g_x1);  SYM(x2, g_x2);
    SYM(hlc, g_hloc); SYM(hin, g_hin);
    SYM(mixh, g_mix_h); SYM(mixl, g_mix_l);
    SYM(qrh, g_qr_h); SYM(qrl, g_qr_l);
    SYM(krh, g_kr_h); SYM(krl, g_kr_l);
    SYM(vrh, g_vr_h); SYM(vrl, g_vr_l);
    SYM(ysh, g_ys_h);
    SYM(h2h, g_h2_h);
    SYM(ffh, g_ff_h);
    SYM(x2h, g_x2h);
    SYM(adh, g_ad_h);
    SYM(quTh, g_quT_h); SYM(quTl, g_quT_l);
    SYM(kuTh, g_kuT_h); SYM(kuTl, g_kuT_l);
    SYM(vuTh, g_vuT_h); SYM(vuTl, g_vuT_l);
    SYM(qvTh, g_qvT_h); SYM(qvTl, g_qvT_l);
    SYM(kvTh, g_kvT_h); SYM(kvTl, g_kvT_l);
    SYM(vvTh, g_vvT_h); SYM(vvTl, g_vvT_l);
    SYM(owTh, g_owT_h);
    SYM(w1Th, g_w1T_h);
    SYM(w2Th, g_w2T_h);
    SYM(adwTh, g_adwT_h); SYM(adwTl, g_adwT_l);
    SYM(auwTh, g_auwT_h);
#undef SYM

    // variants: <BN, WM, WN, PASSES, BIAS, GELU, RES, OUTF32, OUTH, OUTL>
    auto mm_down = mm_h<64,  4, 2, 3, false, false, false, false, true,  true >;
    auto mm_up   = mm_h<128, 2, 4, 3, false, false, false, true,  false, false>;
    auto mm_oprj = mm_h<256, 2, 4, 1, true,  false, true,  true,  false, false>;
    auto mm_ffn1 = mm_h<256, 2, 4, 1, true,  true,  false, false, true,  false>;
    auto mm_ffn2 = mm_h<256, 2, 4, 1, true,  false, true,  true,  true,  false>;
    auto mm_add  = mm_h<32,  8, 1, 2, true,  true,  false, false, true,  false>;
    auto mm_adu  = mm_h<256, 2, 4, 1, true,  false, true,  true,  false, false>;
    cudaFuncSetAttribute(mm_down, cudaFuncAttributeMaxDynamicSharedMemorySize, SM_P3(64));
    cudaFuncSetAttribute(mm_up,   cudaFuncAttributeMaxDynamicSharedMemorySize, SM_P3(128));
    cudaFuncSetAttribute(mm_oprj, cudaFuncAttributeMaxDynamicSharedMemorySize, SM_P1(256));
    cudaFuncSetAttribute(mm_ffn1, cudaFuncAttributeMaxDynamicSharedMemorySize, SM_P1(256));
    cudaFuncSetAttribute(mm_ffn2, cudaFuncAttributeMaxDynamicSharedMemorySize, SM_P1(256));
    cudaFuncSetAttribute(mm_add,  cudaFuncAttributeMaxDynamicSharedMemorySize, SM_P2(32));
    cudaFuncSetAttribute(mm_adu,  cudaFuncAttributeMaxDynamicSharedMemorySize, SM_P1(256));

    dim3 tb(32, 8);
    // ---- weight transposes ----
    transpose_split<<<dim3(RR/32,  CC/32), tb>>>(qu,  CC, RR,  CC,  quTh, quTl);
    transpose_split<<<dim3(RR/32,  CC/32), tb>>>(ku,  CC, RR,  CC,  kuTh, kuTl);
    transpose_split<<<dim3(RR/32,  CC/32), tb>>>(vu,  CC, RR,  CC,  vuTh, vuTl);
    transpose_split<<<dim3(CC/32,  RR/32), tb>>>(qv,  RR, CC,  RR,  qvTh, qvTl);
    transpose_split<<<dim3(CC/32,  RR/32), tb>>>(kvw, RR, CC,  RR,  kvTh, kvTl);
    transpose_split<<<dim3(CC/32,  RR/32), tb>>>(vvw, RR, CC,  RR,  vvTh, vvTl);
    transpose_split<<<dim3(CC/32,  CC/32), tb>>>(out_w, CC, CC, CC, owTh, nullptr);
    transpose_split<<<dim3(FFD/32, CC/32), tb>>>(w1,  CC, FFD, CC,  w1Th, nullptr);
    transpose_split<<<dim3(CC/32,  FFD/32),tb>>>(w2,  FFD, CC, FFD, w2Th, nullptr);
    transpose_split<<<dim3(ARR/32, CC/32), tb>>>(adw, CC, ARR, CC,  adwTh, adwTl);
    transpose_split<<<dim3(CC/32,  64/32), tb>>>(auw, ARR, CC, 64,  auwTh, nullptr);

    // 1) xn = LN(LN(x)); mix = 0.5*(xn + shift(xn)) split to fp16 pair
    ln_kernel<<<MM, 256>>>(x, ln1_g, ln1_b, tm_g, tm_b, xn, nullptr);
    mix_split<<<MM*CC/1024, 256>>>(xn, mixh, mixl);

    // 2) low-rank down-projections (N=64, K=1024), 3-pass, out fp16 pair
    mm_down<<<dim3(1, MM/128), 256, SM_P3(64)>>>(MM, RR, CC, RR, mixh, mixl, quTh, quTl,
                                                 nullptr, qrh, qrl, nullptr, nullptr);
    mm_down<<<dim3(1, MM/128), 256, SM_P3(64)>>>(MM, RR, CC, RR, mixh, mixl, kuTh, kuTl,
                                                 nullptr, krh, krl, nullptr, nullptr);
    mm_down<<<dim3(1, MM/128), 256, SM_P3(64)>>>(MM, RR, CC, RR, mixh, mixl, vuTh, vuTl,
                                                 nullptr, vrh, vrl, nullptr, nullptr);

    // 3) up-projections (N=1024, K=64), 3-pass, out fp32
    mm_up<<<dim3(CC/128, MM/128), 256, SM_P3(128)>>>(MM, CC, RR, 0, qrh, qrl, qvTh, qvTl,
                                                     q, nullptr, nullptr, nullptr, nullptr);
    mm_up<<<dim3(CC/128, MM/128), 256, SM_P3(128)>>>(MM, CC, RR, 0, krh, krl, kvTh, kvTl,
                                                     k, nullptr, nullptr, nullptr, nullptr);
    mm_up<<<dim3(CC/128, MM/128), 256, SM_P3(128)>>>(MM, CC, RR, 0, vrh, vrl, vvTh, vvTl,
                                                     v, nullptr, nullptr, nullptr, nullptr);

    // 4) segmented scan -> ys fp16
    scan_local  <<<(SEG*BC)/256, 256>>>(k, v, td, hlc);
    scan_combine<<<BC/256, 256>>>(hlc, h0, td, hin, out, (long)out_size);
    scan_apply  <<<(SEG*BC)/256, 256>>>(k, v, q, td, hin, ysh);

    // 5) out-proj (1-pass) + bias + residual(x) -> x1 fp32
    mm_oprj<<<dim3(CC/256, MM/128), 256, SM_P1(256)>>>(MM, CC, CC, 0, ysh, nullptr,
                                                       owTh, nullptr, x1, nullptr, nullptr,
                                                       out_b, x);

    // 6) h2 = LN2(x1) -> fp16 hi
    ln_kernel<<<MM, 256>>>(x1, ln2_g, ln2_b, nullptr, nullptr, nullptr, h2h);

    // 7) FFN (1-pass)
    mm_ffn1<<<dim3(FFD/256, MM/128), 256, SM_P1(256)>>>(MM, FFD, CC, FFD, h2h, nullptr,
                                                        w1Th, nullptr, nullptr, ffh, nullptr,
                                                        b1, nullptr);
    mm_ffn2<<<dim3(CC/256, MM/128), 256, SM_P1(256)>>>(MM, CC, FFD, CC, ffh, nullptr,
                                                       w2Th, nullptr, x2, x2h, nullptr,
                                                       b2, x1);

    // 8) adapter: down (2-pass, N=32, K-pad out to 64), up (1-pass, K=64) + res
    mm_add<<<dim3(1, MM/128), 256, SM_P2(32)>>>(MM, ARR, CC, 64, x2h, nullptr, adwTh, adwTl,
                                                nullptr, adh, nullptr, adb, nullptr);
    mm_adu<<<dim3(CC/256, MM/128), 256, SM_P1(256)>>>(MM, CC, 64, 0, adh, nullptr,
                                                      auwTh, nullptr, out, nullptr, nullptr,
                                                      aub, x2);
}

// round 7
// speedup vs baseline: 6.2088x; 1.0634x over previous
#include <cuda_runtime.h>
#include <cuda_fp16.h>
#include <math.h>
#include <stdint.h>

// ---------------- problem constants (fixed shapes) ----------------
#define BB   8
#define TT   2048
#define CC   1024
#define RR   64
#define ARR  32
#define FFD  4096
#define MM   (BB*TT)        // 16384 rows
#define SEG  16
#define LSEG (TT/SEG)       // 128
#define BC   (BB*CC)        // 8192 channels

typedef __half f16;

// ---------------- scratch (static device globals; no allocs) ------
__device__ __align__(256) float g_xn[MM*CC];
__device__ __align__(256) float g_x1[MM*CC];
__device__ __align__(256) float g_x2[MM*CC];
__device__ __align__(256) float g_hloc[SEG*BC];
__device__ __align__(256) float g_hin [SEG*BC];

// fp16 activation buffers
__device__ __align__(256) f16 g_mix_h[MM*CC],  g_mix_l[MM*CC];
__device__ __align__(256) f16 g_qkvr_h[MM*3*RR], g_qkvr_l[MM*3*RR]; // [M,192] q|k|v
__device__ __align__(256) f16 g_qkv[(size_t)3*MM*CC];               // q,k,v fp16
__device__ __align__(256) f16 g_ys_h[MM*CC];
__device__ __align__(256) f16 g_h2_h[MM*CC];
__device__ __align__(256) f16 g_ff_h[(size_t)MM*FFD];
__device__ __align__(256) f16 g_x2h[MM*CC];
__device__ __align__(256) f16 g_ad_h[MM*64];          // K padded 32->64

// fp16 transposed weights ([N,K] K-major)
__device__ __align__(256) f16 g_uT_h[3*RR*CC], g_uT_l[3*RR*CC];   // qu|ku|vu  [192,1024]
__device__ __align__(256) f16 g_vT_h[3*CC*RR], g_vT_l[3*CC*RR];   // qv|kv|vv  3x[1024,64]
__device__ __align__(256) f16 g_owT_h[CC*CC];
__device__ __align__(256) f16 g_w1T_h[(size_t)FFD*CC];
__device__ __align__(256) f16 g_w2T_h[(size_t)CC*FFD];
__device__ __align__(256) f16 g_adwT_h[ARR*CC], g_adwT_l[ARR*CC];
__device__ __align__(256) f16 g_auwT_h[CC*64];        // K padded 32->64

// ---------------- PTX helpers ---------------------------------------
__device__ __forceinline__ uint32_t smem_u32(const void* p) {
    uint32_t a;
    asm("{ .reg .u64 t; cvta.to.shared.u64 t, %1; cvt.u32.u64 %0, t; }" : "=r"(a) : "l"(p));
    return a;
}
#define SWZ128(b) ((b) ^ (((b) >> 3) & 0x70))

__device__ __forceinline__ void cp16(uint32_t dst, const void* src) {
    asm volatile("cp.async.cg.shared.global [%0], [%1], 16;" :: "r"(dst), "l"(src));
}
#define CP_COMMIT()  asm volatile("cp.async.commit_group;" ::: "memory")

__device__ __forceinline__ void ldsm_x4(uint32_t* r, uint32_t addr) {
    asm volatile("ldmatrix.sync.aligned.m8n8.x4.shared.b16 {%0,%1,%2,%3}, [%4];"
                 : "=r"(r[0]), "=r"(r[1]), "=r"(r[2]), "=r"(r[3]) : "r"(addr));
}
__device__ __forceinline__ void mma16816(float* d, const uint32_t* a, const uint32_t* b) {
    asm volatile("mma.sync.aligned.m16n8k16.row.col.f32.f16.f16.f32 "
                 "{%0,%1,%2,%3}, {%4,%5,%6,%7}, {%8,%9}, {%0,%1,%2,%3};"
                 : "+f"(d[0]), "+f"(d[1]), "+f"(d[2]), "+f"(d[3])
                 : "r"(a[0]), "r"(a[1]), "r"(a[2]), "r"(a[3]), "r"(b[0]), "r"(b[1]));
}
__device__ __forceinline__ float tanh_fast(float x) {
    float y;
    asm("tanh.approx.f32 %0, %1;" : "=f"(y) : "f"(x));
    return y;
}

// ---------------- misc helpers --------------------------------------
__device__ __forceinline__ float gelu_tanh(float x) {
    float x3 = x * x * x;
    return 0.5f * x * (1.f + tanh_fast(0.7978845608028654f * (x + 0.044715f * x3)));
}
__device__ __forceinline__ float sigmoid_fast(float x) {
    return 0.5f + 0.5f * tanh_fast(0.5f * x);
}
__device__ __forceinline__ void split2(float x, f16& h, f16& l) {
    h = __float2half_rn(x);
    l = __float2half_rn(x - __half2float(h));
}
__device__ __forceinline__ float block_sum_256(float val, float* sh) {
    int lane = threadIdx.x & 31;
#pragma unroll
    for (int o = 16; o > 0; o >>= 1) val += __shfl_xor_sync(0xffffffffu, val, o);
    if (lane == 0) sh[threadIdx.x >> 5] = val;
    __syncthreads();
    float r = (lane < 8) ? sh[lane] : 0.f;
#pragma unroll
    for (int o = 4; o > 0; o >>= 1) r += __shfl_xor_sync(0xffffffffu, r, o);
    r = __shfl_sync(0xffffffffu, r, 0);
    __syncthreads();
    return r;
}

// ---------------- LayerNorm -----------------------------------------
__global__ void ln_kernel(const float* __restrict__ x,
                          const float* __restrict__ g1, const float* __restrict__ b1,
                          const float* __restrict__ g2, const float* __restrict__ b2,
                          float* __restrict__ out, f16* __restrict__ oh)
{
    __shared__ float sh[8];
    int row = blockIdx.x;
    int tid = threadIdx.x;
    const float* xr = x + (size_t)row * CC;
    float v[4];
#pragma unroll
    for (int i = 0; i < 4; i++) v[i] = xr[tid + i * 256];

#pragma unroll 1
    for (int pass = 0; pass < 2; pass++) {
        const float* gg = pass ? g2 : g1;
        const float* bb = pass ? b2 : b1;
        if (gg == nullptr) break;
        float s = v[0] + v[1] + v[2] + v[3];
        float mean = block_sum_256(s, sh) * (1.f / CC);
        float s2 = 0.f;
#pragma unroll
        for (int i = 0; i < 4; i++) { float d = v[i] - mean; s2 += d * d; }
        float var = block_sum_256(s2, sh) * (1.f / CC);
        float rstd = rsqrtf(var + 1e-5f);
#pragma unroll
        for (int i = 0; i < 4; i++) {
            int idx = tid + i * 256;
            v[i] = (v[i] - mean) * rstd * gg[idx] + bb[idx];
        }
    }
#pragma unroll
    for (int i = 0; i < 4; i++) {
        size_t o = (size_t)row * CC + tid + i * 256;
        if (out) out[o] = v[i];
        if (oh)  oh[o]  = __float2half_rn(v[i]);
    }
}

// ---------------- mix + split ----------------------------------------
__global__ void mix_split(const float* __restrict__ xn,
                          f16* __restrict__ mh, f16* __restrict__ ml)
{
    size_t i = ((size_t)blockIdx.x * 256 + threadIdx.x) * 4;
    int row = (int)(i >> 10);
    int t = row & (TT - 1);
    float4 a = *(const float4*)(xn + i);
    float4 p = make_float4(0.f, 0.f, 0.f, 0.f);
    if (t > 0) p = *(const float4*)(xn + i - CC);
    float m[4] = {0.5f*(a.x+p.x), 0.5f*(a.y+p.y), 0.5f*(a.z+p.z), 0.5f*(a.w+p.w)};
#pragma unroll
    for (int j = 0; j < 4; j++) { f16 h, l; split2(m[j], h, l); mh[i+j] = h; ml[i+j] = l; }
}

// ---------------- weight transpose + split ---------------------------
__global__ void transpose_split(const float* __restrict__ w, int R, int S, int ldout,
                                f16* __restrict__ th, f16* __restrict__ tl)
{
    __shared__ float t[32][33];
    int s0 = blockIdx.x * 32, r0 = blockIdx.y * 32;
#pragma unroll
    for (int i = threadIdx.y; i < 32; i += 8) {
        float v = 0.f;
        if (r0 + i < R) v = w[(size_t)(r0 + i) * S + s0 + threadIdx.x];
        t[i][threadIdx.x] = v;
    }
    __syncthreads();
#pragma unroll
    for (int i = threadIdx.y; i < 32; i += 8) {
        float v = t[threadIdx.x][i];
        size_t o = (size_t)(s0 + i) * ldout + r0 + threadIdx.x;
        f16 h, l; split2(v, h, l);
        th[o] = h;
        if (tl) tl[o] = l;
    }
}

// triple variant: blockIdx.z selects source, output offset z*zoff
__global__ void transpose_split3(const float* __restrict__ w0, const float* __restrict__ w1,
                                 const float* __restrict__ w2,
                                 int R, int S, int ldout, size_t zoff,
                                 f16* __restrict__ th, f16* __restrict__ tl)
{
    __shared__ float t[32][33];
    const float* w = (blockIdx.z == 0) ? w0 : (blockIdx.z == 1) ? w1 : w2;
    th += blockIdx.z * zoff;
    tl += blockIdx.z * zoff;
    int s0 = blockIdx.x * 32, r0 = blockIdx.y * 32;
#pragma unroll
    for (int i = threadIdx.y; i < 32; i += 8) {
        float v = 0.f;
        if (r0 + i < R) v = w[(size_t)(r0 + i) * S + s0 + threadIdx.x];
        t[i][threadIdx.x] = v;
    }
    __syncthreads();
#pragma unroll
    for (int i = threadIdx.y; i < 32; i += 8) {
        float v = t[threadIdx.x][i];
        size_t o = (size_t)(s0 + i) * ldout + r0 + threadIdx.x;
        f16 h, l; split2(v, h, l);
        th[o] = h; tl[o] = l;
    }
}

// ---------------- HMMA fp16 split GEMM --------------------------------
// D[M,N] = A[M,K] @ B[N,K]^T, fp32 accum. STAGES-deep cp.async pipeline.
// PASSES=1: Ah*Bh; =2: Ah*(Bh+Bl); =3: Ah*Bh + Ah*Bl + Al*Bh.
// blockIdx.z batching via az/bz/czf/czh element offsets.
template<int BN, int WMS, int WNS, int PASSES, int S,
         bool BIAS, bool GELU, bool RES, bool OUTF32, bool OUTH, bool OUTL>
__global__ void __launch_bounds__(256, 1)
mm_h(int M, int N, int K, int lda, int ldh,
     size_t az, size_t bz, size_t czf, size_t czh,
     const f16* __restrict__ Ah, const f16* __restrict__ Al,
     const f16* __restrict__ Bh, const f16* __restrict__ Bl,
     float* __restrict__ C, f16* __restrict__ Ch, f16* __restrict__ Cl,
     const float* __restrict__ bias, const float* __restrict__ res)
{
    constexpr int BM = 128;
    constexpr int AT = (PASSES == 3) ? 2 : 1;
    constexpr int BT = (PASSES >= 2) ? 2 : 1;
    constexpr int TMW = BM / WMS;
    constexpr int TNW = BN / WNS;
    constexpr int MT = TMW / 16;
    constexpr int NT = TNW / 8;
    constexpr int A_BYTES = BM * 128;
    constexpr int B_BYTES = BN * 128;
    constexpr int STAGE   = AT * A_BYTES + BT * B_BYTES;

    extern __shared__ char smem[];
    const uint32_t sb = smem_u32(smem);

    const int z = blockIdx.z;
    Ah += (size_t)z * az;
    if (PASSES == 3) Al += (size_t)z * az;
    Bh += (size_t)z * bz;
    if (PASSES >= 2) Bl += (size_t)z * bz;
    if (OUTF32) C  += (size_t)z * czf;
    if (OUTH)   Ch += (size_t)z * czh;
    if (OUTL)   Cl += (size_t)z * czh;

    const int tid  = threadIdx.x;
    const int lane = tid & 31;
    const int warp = tid >> 5;
    const int wm   = warp / WNS;
    const int wn   = warp % WNS;
    const int brow = blockIdx.y * BM;
    const int bcol = blockIdx.x * BN;
    const int NK   = K >> 6;

    float acc[MT][NT][4];
#pragma unroll
    for (int i = 0; i < MT; i++)
#pragma unroll
        for (int j = 0; j < NT; j++)
#pragma unroll
            for (int e = 0; e < 4; e++) acc[i][j][e] = 0.f;

    auto load_stage = [&](int kc, int s) {
        uint32_t base = sb + s * STAGE;
#pragma unroll 2
        for (int i = tid; i < BM * 8; i += 256) {
            int r = i >> 3, j = i & 7;
            size_t go = (size_t)(brow + r) * lda + (size_t)kc * 64 + j * 8;
            uint32_t sw = SWZ128((uint32_t)(r * 128 + j * 16));
            cp16(base + sw, Ah + go);
            if (PASSES == 3) cp16(base + A_BYTES + sw, Al + go);
        }
#pragma unroll 2
        for (int i = tid; i < BN * 8; i += 256) {
            int r = i >> 3, j = i & 7;
            size_t go = (size_t)(bcol + r) * K + (size_t)kc * 64 + j * 8;
            uint32_t sw = SWZ128((uint32_t)(r * 128 + j * 16));
            cp16(base + AT * A_BYTES + sw, Bh + go);
            if (PASSES >= 2) cp16(base + AT * A_BYTES + B_BYTES + sw, Bl + go);
        }
        CP_COMMIT();
    };

    const int npre = (S - 1 < NK) ? S - 1 : NK;
    for (int i = 0; i < npre; i++) load_stage(i, i);
    for (int i = npre; i < S - 1; i++) CP_COMMIT();

    for (int kc = 0; kc < NK; kc++) {
        asm volatile("cp.async.wait_group %0;" :: "n"(S - 2) : "memory");
        __syncthreads();
        if (kc + S - 1 < NK) load_stage(kc + S - 1, (kc + S - 1) % S);
        else                 CP_COMMIT();

        const uint32_t st = sb + (kc % S) * STAGE;
#pragma unroll
        for (int ks = 0; ks < 4; ks++) {
            uint32_t a_h[MT][4], a_l[PASSES == 3 ? MT : 1][4];
#pragma unroll
            for (int mt = 0; mt < MT; mt++) {
                int r = wm * TMW + mt * 16 + (lane & 15);
                uint32_t off = SWZ128((uint32_t)(r * 128 + ks * 32 + ((lane >> 4) << 4)));
                ldsm_x4(a_h[mt], st + off);
                if (PASSES == 3) ldsm_x4(a_l[mt], st + A_BYTES + off);
            }
            uint32_t b_h[NT][2], b_l[PASSES >= 2 ? NT : 1][2];
#pragma unroll
            for (int p = 0; p < NT / 2; p++) {
                int r = wn * TNW + p * 16 + (lane & 7) + ((lane >> 4) << 3);
                uint32_t off = SWZ128((uint32_t)(r * 128 + ks * 32 + (((lane >> 3) & 1) << 4)));
                uint32_t t4[4];
                ldsm_x4(t4, st + AT * A_BYTES + off);
                b_h[2*p][0] = t4[0]; b_h[2*p][1] = t4[1];
                b_h[2*p+1][0] = t4[2]; b_h[2*p+1][1] = t4[3];
                if (PASSES >= 2) {
                    ldsm_x4(t4, st + AT * A_BYTES + B_BYTES + off);
                    b_l[2*p][0] = t4[0]; b_l[2*p][1] = t4[1];
                    b_l[2*p+1][0] = t4[2]; b_l[2*p+1][1] = t4[3];
                }
            }
#pragma unroll
            for (int mt = 0; mt < MT; mt++)
#pragma unroll
                for (int nt = 0; nt < NT; nt++) mma16816(acc[mt][nt], a_h[mt], b_h[nt]);
            if (PASSES >= 2) {
#pragma unroll
                for (int mt = 0; mt < MT; mt++)
#pragma unroll
                    for (int nt = 0; nt < NT; nt++) mma16816(acc[mt][nt], a_h[mt], b_l[nt]);
            }
            if (PASSES == 3) {
#pragma unroll
                for (int mt = 0; mt < MT; mt++)
#pragma unroll
                    for (int nt = 0; nt < NT; nt++) mma16816(acc[mt][nt], a_l[mt], b_h[nt]);
            }
        }
    }

    // ---- epilogue ----
#pragma unroll
    for (int mt = 0; mt < MT; mt++) {
#pragma unroll
        for (int nt = 0; nt < NT; nt++) {
            int r0 = brow + wm * TMW + mt * 16 + (lane >> 2);
            int cg = bcol + wn * TNW + nt * 8 + ((lane & 3) << 1);
#pragma unroll
            for (int h = 0; h < 2; h++) {
                int r = r0 + h * 8;
                float v0 = acc[mt][nt][2*h], v1 = acc[mt][nt][2*h+1];
                if (BIAS) { v0 += bias[cg]; v1 += bias[cg + 1]; }
                if (GELU) { v0 = gelu_tanh(v0); v1 = gelu_tanh(v1); }
                if (RES) {
                    float2 rv = *(const float2*)(res + (size_t)r * N + cg);
                    v0 += rv.x; v1 += rv.y;
                }
                if (OUTF32)
                    *(float2*)(C + (size_t)r * N + cg) = make_float2(v0, v1);
                if (OUTH) {
                    if (OUTL) {
                        f16 h0, l0, h1, l1;
                        split2(v0, h0, l0); split2(v1, h1, l1);
                        __half2 hh; hh.x = h0; hh.y = h1;
                        __half2 ll; ll.x = l0; ll.y = l1;
                        *(__half2*)(Ch + (size_t)r * ldh + cg) = hh;
                        *(__half2*)(Cl + (size_t)r * ldh + cg) = ll;
                    } else {
                        __half2 hh; hh.x = __float2half_rn(v0); hh.y = __float2half_rn(v1);
                        *(__half2*)(Ch + (size_t)r * ldh + cg) = hh;
                    }
                }
            }
        }
    }
    if (OUTH && ldh > N) {
        int pads = (ldh - N) >> 3;
        for (int i = tid; i < BM * pads; i += 256) {
            int r = brow + i / pads;
            int c = N + (i % pads) * 8;
            uint4 zv = make_uint4(0, 0, 0, 0);
            *(uint4*)(Ch + (size_t)r * ldh + c) = zv;
            if (OUTL) *(uint4*)(Cl + (size_t)r * ldh + c) = zv;
        }
    }
}

// ---------------- segmented scan (fp16 q/k/v) -------------------------
__global__ void scan_local(const f16* __restrict__ k, const f16* __restrict__ v,
                           const float* __restrict__ td, float* __restrict__ hloc)
{
    int idx = blockIdx.x * blockDim.x + threadIdx.x;
    int seg = idx / BC;
    int rem = idx - seg * BC;
    int b = rem / CC, c = rem - b * CC;
    float d = expf(-expf(td[c]));
    size_t base = ((size_t)(b * TT + seg * LSEG)) * CC + c;
    float h = 0.f;
#pragma unroll 4
    for (int i = 0; i < LSEG; i++) {
        h = d * h + __half2float(k[base]) * __half2float(v[base]);
        base += CC;
    }
    hloc[idx] = h;
}

__global__ void scan_combine(const float* __restrict__ hloc, const float* __restrict__ h0,
                             const float* __restrict__ td, float* __restrict__ hin,
                             float* __restrict__ out, long out_size)
{
    int rem = blockIdx.x * blockDim.x + threadIdx.x;
    int c = rem & (CC - 1);
    float e = expf(td[c]);
    float dL = expf(-(float)LSEG * e);
    float h = h0[rem];
#pragma unroll
    for (int s = 0; s < SEG; s++) {
        hin[s * BC + rem] = h;
        h = dL * h + hloc[s * BC + rem];
    }
    if (out_size >= (long)MM * CC + BC)
        out[(size_t)MM * CC + rem] = h;
}

__global__ void scan_apply(const f16* __restrict__ k, const f16* __restrict__ v,
                           const f16* __restrict__ q, const float* __restrict__ td,
                           const float* __restrict__ hin, f16* __restrict__ yh)
{
    int idx = blockIdx.x * blockDim.x + threadIdx.x;
    int seg = idx / BC;
    int rem = idx - seg * BC;
    int b = rem / CC, c = rem - b * CC;
    float d = expf(-expf(td[c]));
    float h = hin[seg * BC + rem];
    size_t base = ((size_t)(b * TT + seg * LSEG)) * CC + c;
#pragma unroll 4
    for (int i = 0; i < LSEG; i++) {
        h = d * h + __half2float(k[base]) * __half2float(v[base]);
        yh[base] = __float2half_rn(h * sigmoid_fast(__half2float(q[base])));
        base += CC;
    }
}

// ---------------- launch ----------------------------------------------
#define SMEMSZ(PASSES, BN, S) \
    ((S) * ((((PASSES) == 3 ? 2 : 1) * 128 + (((PASSES) >= 2) ? 2 : 1) * (BN)) * 128))

extern "C" void kernel_launch(void* const* d_in, const int* in_sizes, int n_in,
                              void* d_out, int out_size)
{
    const float* x     = (const float*)d_in[0];
    const float* h0    = (const float*)d_in[1];
    const float* ln1_g = (const float*)d_in[2];
    const float* ln1_b = (const float*)d_in[3];
    const float* tm_g  = (const float*)d_in[4];
    const float* tm_b  = (const float*)d_in[5];
    const float* qu    = (const float*)d_in[6];
    const float* qv    = (const float*)d_in[7];
    const float* ku    = (const float*)d_in[8];
    const float* kvw   = (const float*)d_in[9];
    const float* vu    = (const float*)d_in[10];
    const float* vvw   = (const float*)d_in[11];
    const float* td    = (const float*)d_in[12];
    const float* out_w = (const float*)d_in[13];
    const float* out_b = (const float*)d_in[14];
    const float* ln2_g = (const float*)d_in[15];
    const float* ln2_b = (const float*)d_in[16];
    const float* w1    = (const float*)d_in[17];
    const float* b1    = (const float*)d_in[18];
    const float* w2    = (const float*)d_in[19];
    const float* b2    = (const float*)d_in[20];
    const float* adw   = (const float*)d_in[21];
    const float* adb   = (const float*)d_in[22];
    const float* auw   = (const float*)d_in[23];
    const float* aub   = (const float*)d_in[24];
    float* out = (float*)d_out;

    void* p;
#define SYM(var, sym) cudaGetSymbolAddress(&p, sym); auto* var = (decltype(&sym[0]))p
    SYM(xn,  g_xn);  SYM(x1, g_x1);  SYM(x2, g_x2);
    SYM(hlc, g_hloc); SYM(hin, g_hin);
    SYM(mixh, g_mix_h); SYM(mixl, g_mix_l);
    SYM(qkvrh, g_qkvr_h); SYM(qkvrl, g_qkvr_l);
    SYM(qkv,  g_qkv);
    SYM(ysh, g_ys_h);
    SYM(h2h, g_h2_h);
    SYM(ffh, g_ff_h);
    SYM(x2h, g_x2h);
    SYM(adh, g_ad_h);
    SYM(uTh, g_uT_h); SYM(uTl, g_uT_l);
    SYM(vTh, g_vT_h); SYM(vTl, g_vT_l);
    SYM(owTh, g_owT_h);
    SYM(w1Th, g_w1T_h);
    SYM(w2Th, g_w2T_h);
    SYM(adwTh, g_adwT_h); SYM(adwTl, g_adwT_l);
    SYM(auwTh, g_auwT_h);
#undef SYM
    f16* qf = qkv;
    f16* kf = qkv + (size_t)MM * CC;
    f16* vf = qkv + (size_t)2 * MM * CC;

    // variants: <BN, WM, WN, PASSES, STAGES, BIAS, GELU, RES, OUTF32, OUTH, OUTL>
    auto mm_down = mm_h<64,  4, 2, 3, 3, false, false, false, false, true,  true >;
    auto mm_up   = mm_h<128, 2, 4, 3, 2, false, false, false, false, true,  false>;
    auto mm_oprj = mm_h<256, 2, 4, 1, 3, true,  false, true,  true,  false, false>;
    auto mm_ffn1 = mm_h<256, 2, 4, 1, 3, true,  true,  false, false, true,  false>;
    auto mm_ffn2 = mm_h<256, 2, 4, 1, 3, true,  false, true,  true,  true,  false>;
    auto mm_add  = mm_h<32,  8, 1, 2, 3, true,  true,  false, false, true,  false>;
    auto mm_adu  = mm_h<256, 2, 4, 1, 2, true,  false, true,  true,  false, false>;
    cudaFuncSetAttribute(mm_down, cudaFuncAttributeMaxDynamicSharedMemorySize, SMEMSZ(3,64,3));
    cudaFuncSetAttribute(mm_up,   cudaFuncAttributeMaxDynamicSharedMemorySize, SMEMSZ(3,128,2));
    cudaFuncSetAttribute(mm_oprj, cudaFuncAttributeMaxDynamicSharedMemorySize, SMEMSZ(1,256,3));
    cudaFuncSetAttribute(mm_ffn1, cudaFuncAttributeMaxDynamicSharedMemorySize, SMEMSZ(1,256,3));
    cudaFuncSetAttribute(mm_ffn2, cudaFuncAttributeMaxDynamicSharedMemorySize, SMEMSZ(1,256,3));
    cudaFuncSetAttribute(mm_add,  cudaFuncAttributeMaxDynamicSharedMemorySize, SMEMSZ(2,32,3));
    cudaFuncSetAttribute(mm_adu,  cudaFuncAttributeMaxDynamicSharedMemorySize, SMEMSZ(1,256,2));

    dim3 tb(32, 8);
    // ---- weight transposes ----
    transpose_split3<<<dim3(RR/32, CC/32, 3), tb>>>(qu, ku, vu, CC, RR, CC,
                                                    (size_t)RR*CC, uTh, uTl);
    transpose_split3<<<dim3(CC/32, RR/32, 3), tb>>>(qv, kvw, vvw, RR, CC, RR,
                                                    (size_t)CC*RR, vTh, vTl);
    transpose_split<<<dim3(CC/32,  CC/32), tb>>>(out_w, CC, CC, CC, owTh, nullptr);
    transpose_split<<<dim3(FFD/32, CC/32), tb>>>(w1,  CC, FFD, CC,  w1Th, nullptr);
    transpose_split<<<dim3(CC/32,  FFD/32),tb>>>(w2,  FFD, CC, FFD, w2Th, nullptr);
    transpose_split<<<dim3(ARR/32, CC/32), tb>>>(adw, CC, ARR, CC,  adwTh, adwTl);
    transpose_split<<<dim3(CC/32,  64/32), tb>>>(auw, ARR, CC, 64,  auwTh, nullptr);

    // 1) xn = LN(LN(x)); mix split to fp16 pair
    ln_kernel<<<MM, 256>>>(x, ln1_g, ln1_b, tm_g, tm_b, xn, nullptr);
    mix_split<<<MM*CC/1024, 256>>>(xn, mixh, mixl);

    // 2) fused low-rank down-projections: [M,1024] @ [192,1024]^T -> [M,192]
    mm_down<<<dim3(3, MM/128), 256, SMEMSZ(3,64,3)>>>(
        MM, 3*RR, CC, CC, 3*RR, 0, 0, 0, 0,
        mixh, mixl, uTh, uTl, nullptr, qkvrh, qkvrl, nullptr, nullptr);

    // 3) batched up-projections (z = q,k,v): [M,64] @ [1024,64]^T -> fp16
    mm_up<<<dim3(CC/128, MM/128, 3), 256, SMEMSZ(3,128,2)>>>(
        MM, CC, RR, 3*RR, CC, RR, (size_t)CC*RR, 0, (size_t)MM*CC,
        qkvrh, qkvrl, vTh, vTl, nullptr, qkv, nullptr, nullptr, nullptr);

    // 4) segmented scan -> ys fp16
    scan_local  <<<(SEG*BC)/256, 256>>>(kf, vf, td, hlc);
    scan_combine<<<BC/256, 256>>>(hlc, h0, td, hin, out, (long)out_size);
    scan_apply  <<<(SEG*BC)/256, 256>>>(kf, vf, qf, td, hin, ysh);

    // 5) out-proj (1-pass) + bias + residual(x) -> x1 fp32
    mm_oprj<<<dim3(CC/256, MM/128), 256, SMEMSZ(1,256,3)>>>(
        MM, CC, CC, CC, 0, 0, 0, 0, 0,
        ysh, nullptr, owTh, nullptr, x1, nullptr, nullptr, out_b, x);

    // 6) h2 = LN2(x1) -> fp16
    ln_kernel<<<MM, 256>>>(x1, ln2_g, ln2_b, nullptr, nullptr, nullptr, h2h);

    // 7) FFN (1-pass)
    mm_ffn1<<<dim3(FFD/256, MM/128), 256, SMEMSZ(1,256,3)>>>(
        MM, FFD, CC, CC, FFD, 0, 0, 0, 0,
        h2h, nullptr, w1Th, nullptr, nullptr, ffh, nullptr, b1, nullptr);
    mm_ffn2<<<dim3(CC/256, MM/128), 256, SMEMSZ(1,256,3)>>>(
        MM, CC, FFD, FFD, CC, 0, 0, 0, 0,
        ffh, nullptr, w2Th, nullptr, x2, x2h, nullptr, b2, x1);

    // 8) adapter: down (2-pass, N=32 pad 64) then up (1-pass) + residual
    mm_add<<<dim3(1, MM/128), 256, SMEMSZ(2,32,3)>>>(
        MM, ARR, CC, CC, 64, 0, 0, 0, 0,
        x2h, nullptr, adwTh, adwTl, nullptr, adh, nullptr, adb, nullptr);
    mm_adu<<<dim3(CC/256, MM/128), 256, SMEMSZ(1,256,2)>>>(
        MM, CC, 64, 64, 0, 0, 0, 0, 0,
        adh, nullptr, auwTh, nullptr, out, nullptr, nullptr, aub, x2);
}

// round 8
// speedup vs baseline: 7.5030x; 1.2084x over previous
#include <cuda_runtime.h>
#include <cuda_fp16.h>
#include <math.h>
#include <stdint.h>

// ---------------- problem constants (fixed shapes) ----------------
#define BB   8
#define TT   2048
#define CC   1024
#define RR   64
#define ARR  32
#define FFD  4096
#define MM   (BB*TT)        // 16384 rows
#define SEG  64
#define LSEG (TT/SEG)       // 32
#define BC   (BB*CC)        // 8192 channels

typedef __half f16;

// ---------------- scratch (static device globals; no allocs) ------
__device__ __align__(256) float g_xn[MM*CC];
__device__ __align__(256) float g_x1[MM*CC];
__device__ __align__(256) float g_x2[MM*CC];
__device__ __align__(256) float g_hloc[SEG*BC];
__device__ __align__(256) float g_hin [SEG*BC];

// fp16 activation buffers
__device__ __align__(256) f16 g_mix_h[MM*CC];
__device__ __align__(256) f16 g_qkvr_h[MM*3*RR];                 // [M,192] q|k|v
__device__ __align__(256) f16 g_qkv[(size_t)3*MM*CC];            // q,k,v fp16
__device__ __align__(256) f16 g_ys_h[MM*CC];
__device__ __align__(256) f16 g_h2_h[MM*CC];
__device__ __align__(256) f16 g_ff_h[(size_t)MM*FFD];
__device__ __align__(256) f16 g_x2h[MM*CC];
__device__ __align__(256) f16 g_ad_h[MM*64];                     // K padded 32->64

// fp16 transposed weights ([N,K] K-major)
__device__ __align__(256) f16 g_uT_h[3*RR*CC], g_uT_l[3*RR*CC];  // qu|ku|vu [192,1024]
__device__ __align__(256) f16 g_vT_h[3*CC*RR], g_vT_l[3*CC*RR];  // qv|kv|vv 3x[1024,64]
__device__ __align__(256) f16 g_owT_h[CC*CC];
__device__ __align__(256) f16 g_w1T_h[(size_t)FFD*CC];
__device__ __align__(256) f16 g_w2T_h[(size_t)CC*FFD];
__device__ __align__(256) f16 g_adwT_h[ARR*CC], g_adwT_l[ARR*CC];
__device__ __align__(256) f16 g_auwT_h[CC*64];                   // K padded 32->64

// ---------------- PTX helpers ---------------------------------------
__device__ __forceinline__ uint32_t smem_u32(const void* p) {
    uint32_t a;
    asm("{ .reg .u64 t; cvta.to.shared.u64 t, %1; cvt.u32.u64 %0, t; }" : "=r"(a) : "l"(p));
    return a;
}
#define SWZ128(b) ((b) ^ (((b) >> 3) & 0x70))

__device__ __forceinline__ void cp16(uint32_t dst, const void* src) {
    asm volatile("cp.async.cg.shared.global [%0], [%1], 16;" :: "r"(dst), "l"(src));
}
#define CP_COMMIT()  asm volatile("cp.async.commit_group;" ::: "memory")

__device__ __forceinline__ void ldsm_x4(uint32_t* r, uint32_t addr) {
    asm volatile("ldmatrix.sync.aligned.m8n8.x4.shared.b16 {%0,%1,%2,%3}, [%4];"
                 : "=r"(r[0]), "=r"(r[1]), "=r"(r[2]), "=r"(r[3]) : "r"(addr));
}
__device__ __forceinline__ void mma16816(float* d, const uint32_t* a, const uint32_t* b) {
    asm volatile("mma.sync.aligned.m16n8k16.row.col.f32.f16.f16.f32 "
                 "{%0,%1,%2,%3}, {%4,%5,%6,%7}, {%8,%9}, {%0,%1,%2,%3};"
                 : "+f"(d[0]), "+f"(d[1]), "+f"(d[2]), "+f"(d[3])
                 : "r"(a[0]), "r"(a[1]), "r"(a[2]), "r"(a[3]), "r"(b[0]), "r"(b[1]));
}
__device__ __forceinline__ float tanh_fast(float x) {
    float y;
    asm("tanh.approx.f32 %0, %1;" : "=f"(y) : "f"(x));
    return y;
}

// ---------------- misc helpers --------------------------------------
__device__ __forceinline__ float gelu_tanh(float x) {
    float x3 = x * x * x;
    return 0.5f * x * (1.f + tanh_fast(0.7978845608028654f * (x + 0.044715f * x3)));
}
__device__ __forceinline__ float sigmoid_fast(float x) {
    return 0.5f + 0.5f * tanh_fast(0.5f * x);
}
__device__ __forceinline__ void split2(float x, f16& h, f16& l) {
    h = __float2half_rn(x);
    l = __float2half_rn(x - __half2float(h));
}
__device__ __forceinline__ float block_sum_256(float val, float* sh) {
    int lane = threadIdx.x & 31;
#pragma unroll
    for (int o = 16; o > 0; o >>= 1) val += __shfl_xor_sync(0xffffffffu, val, o);
    if (lane == 0) sh[threadIdx.x >> 5] = val;
    __syncthreads();
    float r = (lane < 8) ? sh[lane] : 0.f;
#pragma unroll
    for (int o = 4; o > 0; o >>= 1) r += __shfl_xor_sync(0xffffffffu, r, o);
    r = __shfl_sync(0xffffffffu, r, 0);
    __syncthreads();
    return r;
}

// ---------------- LayerNorm (float4-vectorized) ----------------------
__global__ void ln_kernel(const float* __restrict__ x,
                          const float* __restrict__ g1, const float* __restrict__ b1,
                          const float* __restrict__ g2, const float* __restrict__ b2,
                          float* __restrict__ out, f16* __restrict__ oh)
{
    __shared__ float sh[8];
    int row = blockIdx.x;
    int tid = threadIdx.x;
    float4 v = *(const float4*)(x + (size_t)row * CC + tid * 4);

#pragma unroll 1
    for (int pass = 0; pass < 2; pass++) {
        const float* gg = pass ? g2 : g1;
        const float* bb = pass ? b2 : b1;
        if (gg == nullptr) break;
        float mean = block_sum_256(v.x + v.y + v.z + v.w, sh) * (1.f / CC);
        float dx = v.x - mean, dy = v.y - mean, dz = v.z - mean, dw = v.w - mean;
        float var = block_sum_256(dx*dx + dy*dy + dz*dz + dw*dw, sh) * (1.f / CC);
        float rstd = rsqrtf(var + 1e-5f);
        float4 gv = *(const float4*)(gg + tid * 4);
        float4 bv = *(const float4*)(bb + tid * 4);
        v.x = dx * rstd * gv.x + bv.x;
        v.y = dy * rstd * gv.y + bv.y;
        v.z = dz * rstd * gv.z + bv.z;
        v.w = dw * rstd * gv.w + bv.w;
    }
    size_t o = (size_t)row * CC + tid * 4;
    if (out) *(float4*)(out + o) = v;
    if (oh) {
        __half2 h01 = __floats2half2_rn(v.x, v.y);
        __half2 h23 = __floats2half2_rn(v.z, v.w);
        uint2 u;
        u.x = *(uint32_t*)&h01; u.y = *(uint32_t*)&h23;
        *(uint2*)(oh + o) = u;
    }
}

// ---------------- mix (8 elems/thread, fp16-hi output only) ----------
__global__ void mix_split(const float* __restrict__ xn, f16* __restrict__ mh)
{
    size_t i = ((size_t)blockIdx.x * 256 + threadIdx.x) * 8;
    int row = (int)(i >> 10);
    int t = row & (TT - 1);
    float4 a0 = *(const float4*)(xn + i);
    float4 a1 = *(const float4*)(xn + i + 4);
    float4 p0 = make_float4(0.f, 0.f, 0.f, 0.f), p1 = p0;
    if (t > 0) {
        p0 = *(const float4*)(xn + i - CC);
        p1 = *(const float4*)(xn + i - CC + 4);
    }
    __half2 h0 = __floats2half2_rn(0.5f*(a0.x+p0.x), 0.5f*(a0.y+p0.y));
    __half2 h1 = __floats2half2_rn(0.5f*(a0.z+p0.z), 0.5f*(a0.w+p0.w));
    __half2 h2 = __floats2half2_rn(0.5f*(a1.x+p1.x), 0.5f*(a1.y+p1.y));
    __half2 h3 = __floats2half2_rn(0.5f*(a1.z+p1.z), 0.5f*(a1.w+p1.w));
    uint4 u;
    u.x = *(uint32_t*)&h0; u.y = *(uint32_t*)&h1;
    u.z = *(uint32_t*)&h2; u.w = *(uint32_t*)&h3;
    *(uint4*)(mh + i) = u;
}

// ---------------- weight transpose + split (float2/half2) ------------
__global__ void transpose_split(const float* __restrict__ w, int R, int S, int ldout,
                                f16* __restrict__ th, f16* __restrict__ tl)
{
    __shared__ float t[32][33];
    int s0 = blockIdx.x * 32, r0 = blockIdx.y * 32;
    int tx = threadIdx.x, ty = threadIdx.y;   // (16,16)
#pragma unroll
    for (int i = ty; i < 32; i += 16) {
        float2 v = make_float2(0.f, 0.f);
        if (r0 + i < R) v = *(const float2*)(w + (size_t)(r0 + i) * S + s0 + tx * 2);
        t[i][tx*2] = v.x; t[i][tx*2+1] = v.y;
    }
    __syncthreads();
#pragma unroll
    for (int i = ty; i < 32; i += 16) {
        float a = t[tx*2][i], b = t[tx*2+1][i];
        size_t o = (size_t)(s0 + i) * ldout + r0 + tx * 2;
        f16 ha, la, hb, lb; split2(a, ha, la); split2(b, hb, lb);
        __half2 hh; hh.x = ha; hh.y = hb;
        *(__half2*)(th + o) = hh;
        if (tl) { __half2 ll; ll.x = la; ll.y = lb; *(__half2*)(tl + o) = ll; }
    }
}

// triple variant: blockIdx.z selects source, output offset z*zoff
__global__ void transpose_split3(const float* __restrict__ w0, const float* __restrict__ w1,
                                 const float* __restrict__ w2,
                                 int R, int S, int ldout, size_t zoff,
                                 f16* __restrict__ th, f16* __restrict__ tl)
{
    __shared__ float t[32][33];
    const float* w = (blockIdx.z == 0) ? w0 : (blockIdx.z == 1) ? w1 : w2;
    th += blockIdx.z * zoff;
    tl += blockIdx.z * zoff;
    int s0 = blockIdx.x * 32, r0 = blockIdx.y * 32;
    int tx = threadIdx.x, ty = threadIdx.y;
#pragma unroll
    for (int i = ty; i < 32; i += 16) {
        float2 v = make_float2(0.f, 0.f);
        if (r0 + i < R) v = *(const float2*)(w + (size_t)(r0 + i) * S + s0 + tx * 2);
        t[i][tx*2] = v.x; t[i][tx*2+1] = v.y;
    }
    __syncthreads();
#pragma unroll
    for (int i = ty; i < 32; i += 16) {
        float a = t[tx*2][i], b = t[tx*2+1][i];
        size_t o = (size_t)(s0 + i) * ldout + r0 + tx * 2;
        f16 ha, la, hb, lb; split2(a, ha, la); split2(b, hb, lb);
        __half2 hh; hh.x = ha; hh.y = hb;
        *(__half2*)(th + o) = hh;
        __half2 ll; ll.x = la; ll.y = lb;
        *(__half2*)(tl + o) = ll;
    }
}

// ---------------- HMMA fp16 split GEMM --------------------------------
// D[M,N] = A[M,K] @ B[N,K]^T, fp32 accum. S-stage cp.async pipeline.
// PASSES=1: Ah*Bh; =2: Ah*(Bh+Bl); =3: Ah*Bh + Ah*Bl + Al*Bh.
template<int BN, int WMS, int WNS, int PASSES, int S,
         bool BIAS, bool GELU, bool RES, bool OUTF32, bool OUTH, bool OUTL>
__global__ void __launch_bounds__(256, 2)
mm_h(int M, int N, int K, int lda, int ldh,
     size_t az, size_t bz, size_t czf, size_t czh,
     const f16* __restrict__ Ah, const f16* __restrict__ Al,
     const f16* __restrict__ Bh, const f16* __restrict__ Bl,
     float* __restrict__ C, f16* __restrict__ Ch, f16* __restrict__ Cl,
     const float* __restrict__ bias, const float* __restrict__ res)
{
    constexpr int BM = 128;
    constexpr int AT = (PASSES == 3) ? 2 : 1;
    constexpr int BT = (PASSES >= 2) ? 2 : 1;
    constexpr int TMW = BM / WMS;
    constexpr int TNW = BN / WNS;
    constexpr int MT = TMW / 16;
    constexpr int NT = TNW / 8;
    constexpr int A_BYTES = BM * 128;
    constexpr int B_BYTES = BN * 128;
    constexpr int STAGE   = AT * A_BYTES + BT * B_BYTES;

    extern __shared__ char smem[];
    const uint32_t sb = smem_u32(smem);

    const int z = blockIdx.z;
    Ah += (size_t)z * az;
    if (PASSES == 3) Al += (size_t)z * az;
    Bh += (size_t)z * bz;
    if (PASSES >= 2) Bl += (size_t)z * bz;
    if (OUTF32) C  += (size_t)z * czf;
    if (OUTH)   Ch += (size_t)z * czh;
    if (OUTL)   Cl += (size_t)z * czh;

    const int tid  = threadIdx.x;
    const int lane = tid & 31;
    const int warp = tid >> 5;
    const int wm   = warp / WNS;
    const int wn   = warp % WNS;
    const int brow = blockIdx.y * BM;
    const int bcol = blockIdx.x * BN;
    const int NK   = K >> 6;

    float acc[MT][NT][4];
#pragma unroll
    for (int i = 0; i < MT; i++)
#pragma unroll
        for (int j = 0; j < NT; j++)
#pragma unroll
            for (int e = 0; e < 4; e++) acc[i][j][e] = 0.f;

    auto load_stage = [&](int kc, int s) {
        uint32_t base = sb + s * STAGE;
#pragma unroll 2
        for (int i = tid; i < BM * 8; i += 256) {
            int r = i >> 3, j = i & 7;
            size_t go = (size_t)(brow + r) * lda + (size_t)kc * 64 + j * 8;
            uint32_t sw = SWZ128((uint32_t)(r * 128 + j * 16));
            cp16(base + sw, Ah + go);
            if (PASSES == 3) cp16(base + A_BYTES + sw, Al + go);
        }
#pragma unroll 2
        for (int i = tid; i < BN * 8; i += 256) {
            int r = i >> 3, j = i & 7;
            size_t go = (size_t)(bcol + r) * K + (size_t)kc * 64 + j * 8;
            uint32_t sw = SWZ128((uint32_t)(r * 128 + j * 16));
            cp16(base + AT * A_BYTES + sw, Bh + go);
            if (PASSES >= 2) cp16(base + AT * A_BYTES + B_BYTES + sw, Bl + go);
        }
        CP_COMMIT();
    };

    const int npre = (S - 1 < NK) ? S - 1 : NK;
    for (int i = 0; i < npre; i++) load_stage(i, i);
    for (int i = npre; i < S - 1; i++) CP_COMMIT();

    for (int kc = 0; kc < NK; kc++) {
        asm volatile("cp.async.wait_group %0;" :: "n"(S - 2) : "memory");
        __syncthreads();
        if (kc + S - 1 < NK) load_stage(kc + S - 1, (kc + S - 1) % S);
        else                 CP_COMMIT();

        const uint32_t st = sb + (kc % S) * STAGE;
#pragma unroll
        for (int ks = 0; ks < 4; ks++) {
            uint32_t a_h[MT][4], a_l[PASSES == 3 ? MT : 1][4];
#pragma unroll
            for (int mt = 0; mt < MT; mt++) {
                int r = wm * TMW + mt * 16 + (lane & 15);
                uint32_t off = SWZ128((uint32_t)(r * 128 + ks * 32 + ((lane >> 4) << 4)));
                ldsm_x4(a_h[mt], st + off);
                if (PASSES == 3) ldsm_x4(a_l[mt], st + A_BYTES + off);
            }
            uint32_t b_h[NT][2], b_l[PASSES >= 2 ? NT : 1][2];
#pragma unroll
            for (int p = 0; p < NT / 2; p++) {
                int r = wn * TNW + p * 16 + (lane & 7) + ((lane >> 4) << 3);
                uint32_t off = SWZ128((uint32_t)(r * 128 + ks * 32 + (((lane >> 3) & 1) << 4)));
                uint32_t t4[4];
                ldsm_x4(t4, st + AT * A_BYTES + off);
                b_h[2*p][0] = t4[0]; b_h[2*p][1] = t4[1];
                b_h[2*p+1][0] = t4[2]; b_h[2*p+1][1] = t4[3];
                if (PASSES >= 2) {
                    ldsm_x4(t4, st + AT * A_BYTES + B_BYTES + off);
                    b_l[2*p][0] = t4[0]; b_l[2*p][1] = t4[1];
                    b_l[2*p+1][0] = t4[2]; b_l[2*p+1][1] = t4[3];
                }
            }
#pragma unroll
            for (int mt = 0; mt < MT; mt++)
#pragma unroll
                for (int nt = 0; nt < NT; nt++) mma16816(acc[mt][nt], a_h[mt], b_h[nt]);
            if (PASSES >= 2) {
#pragma unroll
                for (int mt = 0; mt < MT; mt++)
#pragma unroll
                    for (int nt = 0; nt < NT; nt++) mma16816(acc[mt][nt], a_h[mt], b_l[nt]);
            }
            if (PASSES == 3) {
#pragma unroll
                for (int mt = 0; mt < MT; mt++)
#pragma unroll
                    for (int nt = 0; nt < NT; nt++) mma16816(acc[mt][nt], a_l[mt], b_h[nt]);
            }
        }
    }

    // ---- epilogue ----
#pragma unroll
    for (int mt = 0; mt < MT; mt++) {
#pragma unroll
        for (int nt = 0; nt < NT; nt++) {
            int r0 = brow + wm * TMW + mt * 16 + (lane >> 2);
            int cg = bcol + wn * TNW + nt * 8 + ((lane & 3) << 1);
#pragma unroll
            for (int h = 0; h < 2; h++) {
                int r = r0 + h * 8;
                float v0 = acc[mt][nt][2*h], v1 = acc[mt][nt][2*h+1];
                if (BIAS) { v0 += bias[cg]; v1 += bias[cg + 1]; }
                if (GELU) { v0 = gelu_tanh(v0); v1 = gelu_tanh(v1); }
                if (RES) {
                    float2 rv = *(const float2*)(res + (size_t)r * N + cg);
                    v0 += rv.x; v1 += rv.y;
                }
                if (OUTF32)
                    *(float2*)(C + (size_t)r * N + cg) = make_float2(v0, v1);
                if (OUTH) {
                    if (OUTL) {
                        f16 h0, l0, h1, l1;
                        split2(v0, h0, l0); split2(v1, h1, l1);
                        __half2 hh; hh.x = h0; hh.y = h1;
                        __half2 ll; ll.x = l0; ll.y = l1;
                        *(__half2*)(Ch + (size_t)r * ldh + cg) = hh;
                        *(__half2*)(Cl + (size_t)r * ldh + cg) = ll;
                    } else {
                        __half2 hh; hh.x = __float2half_rn(v0); hh.y = __float2half_rn(v1);
                        *(__half2*)(Ch + (size_t)r * ldh + cg) = hh;
                    }
                }
            }
        }
    }
    if (OUTH && ldh > N) {
        int pads = (ldh - N) >> 3;
        for (int i = tid; i < BM * pads; i += 256) {
            int r = brow + i / pads;
            int c = N + (i % pads) * 8;
            uint4 zv = make_uint4(0, 0, 0, 0);
            *(uint4*)(Ch + (size_t)r * ldh + c) = zv;
            if (OUTL) *(uint4*)(Cl + (size_t)r * ldh + c) = zv;
        }
    }
}

// ---------------- segmented scan (8 channels/thread, uint4 I/O) ------
__global__ void scan_local(const f16* __restrict__ k, const f16* __restrict__ v,
                           const float* __restrict__ td, float* __restrict__ hloc)
{
    int idx = blockIdx.x * blockDim.x + threadIdx.x;   // < SEG*BB*(CC/8)
    int c8 = idx & (CC/8 - 1);
    int rest = idx >> 7;
    int b = rest & (BB - 1);
    int seg = rest >> 3;
    int c0 = c8 * 8;
    float4 t0 = *(const float4*)(td + c0);
    float4 t1 = *(const float4*)(td + c0 + 4);
    float d[8] = {expf(-expf(t0.x)), expf(-expf(t0.y)), expf(-expf(t0.z)), expf(-expf(t0.w)),
                  expf(-expf(t1.x)), expf(-expf(t1.y)), expf(-expf(t1.z)), expf(-expf(t1.w))};
    float h[8] = {0.f,0.f,0.f,0.f,0.f,0.f,0.f,0.f};
    size_t base = ((size_t)(b * TT + seg * LSEG)) * CC + c0;
#pragma unroll 4
    for (int i = 0; i < LSEG; i++) {
        uint4 ku = *(const uint4*)(k + base);
        uint4 vu = *(const uint4*)(v + base);
        const __half2* kh = (const __half2*)&ku;
        const __half2* vh = (const __half2*)&vu;
#pragma unroll
        for (int j = 0; j < 4; j++) {
            float2 kf = __half22float2(kh[j]);
            float2 vf = __half22float2(vh[j]);
            h[2*j]   = d[2*j]   * h[2*j]   + kf.x * vf.x;
            h[2*j+1] = d[2*j+1] * h[2*j+1] + kf.y * vf.y;
        }
        base += CC;
    }
    int o = seg * BC + b * CC + c0;
    *(float4*)(hloc + o)     = make_float4(h[0], h[1], h[2], h[3]);
    *(float4*)(hloc + o + 4) = make_float4(h[4], h[5], h[6], h[7]);
}

__global__ void scan_combine(const float* __restrict__ hloc, const float* __restrict__ h0,
                             const float* __restrict__ td, float* __restrict__ hin,
                             float* __restrict__ out, long out_size)
{
    int rem = blockIdx.x * blockDim.x + threadIdx.x;   // < BC
    int c = rem & (CC - 1);
    float e = expf(td[c]);
    float dL = expf(-(float)LSEG * e);
    float h = h0[rem];
#pragma unroll
    for (int s = 0; s < SEG; s++) {
        hin[s * BC + rem] = h;
        h = dL * h + hloc[s * BC + rem];
    }
    if (out_size >= (long)MM * CC + BC)
        out[(size_t)MM * CC + rem] = h;
}

__global__ void scan_apply(const f16* __restrict__ k, const f16* __restrict__ v,
                           const f16* __restrict__ q, const float* __restrict__ td,
                           const float* __restrict__ hin, f16* __restrict__ yh)
{
    int idx = blockIdx.x * blockDim.x + threadIdx.x;
    int c8 = idx & (CC/8 - 1);
    int rest = idx >> 7;
    int b = rest & (BB - 1);
    int seg = rest >> 3;
    int c0 = c8 * 8;
    float4 t0 = *(const float4*)(td + c0);
    float4 t1 = *(const float4*)(td + c0 + 4);
    float d[8] = {expf(-expf(t0.x)), expf(-expf(t0.y)), expf(-expf(t0.z)), expf(-expf(t0.w)),
                  expf(-expf(t1.x)), expf(-expf(t1.y)), expf(-expf(t1.z)), expf(-expf(t1.w))};
    int ho = seg * BC + b * CC + c0;
    float4 h03 = *(const float4*)(hin + ho);
    float4 h47 = *(const float4*)(hin + ho + 4);
    float h[8] = {h03.x, h03.y, h03.z, h03.w, h47.x, h47.y, h47.z, h47.w};
    size_t base = ((size_t)(b * TT + seg * LSEG)) * CC + c0;
#pragma unroll 4
    for (int i = 0; i < LSEG; i++) {
        uint4 ku = *(const uint4*)(k + base);
        uint4 vu = *(const uint4*)(v + base);
        uint4 qu = *(const uint4*)(q + base);
        const __half2* kh = (const __half2*)&ku;
        const __half2* vh = (const __half2*)&vu;
        const __half2* qh = (const __half2*)&qu;
        uint4 yo;
        uint32_t* yp = (uint32_t*)&yo;
#pragma unroll
        for (int j = 0; j < 4; j++) {
            float2 kf = __half22float2(kh[j]);
            float2 vf = __half22float2(vh[j]);
            float2 qf = __half22float2(qh[j]);
            h[2*j]   = d[2*j]   * h[2*j]   + kf.x * vf.x;
            h[2*j+1] = d[2*j+1] * h[2*j+1] + kf.y * vf.y;
            __half2 yv = __floats2half2_rn(h[2*j]   * sigmoid_fast(qf.x),
                                           h[2*j+1] * sigmoid_fast(qf.y));
            yp[j] = *(uint32_t*)&yv;
        }
        *(uint4*)(yh + base) = yo;
        base += CC;
    }
}

// ---------------- launch ----------------------------------------------
#define SMEMSZ(PASSES, BN, S) \
    ((S) * ((((PASSES) == 3 ? 2 : 1) * 128 + (((PASSES) >= 2) ? 2 : 1) * (BN)) * 128))

extern "C" void kernel_launch(void* const* d_in, const int* in_sizes, int n_in,
                              void* d_out, int out_size)
{
    const float* x     = (const float*)d_in[0];
    const float* h0    = (const float*)d_in[1];
    const float* ln1_g = (const float*)d_in[2];
    const float* ln1_b = (const float*)d_in[3];
    const float* tm_g  = (const float*)d_in[4];
    const float* tm_b  = (const float*)d_in[5];
    const float* qu    = (const float*)d_in[6];
    const float* qv    = (const float*)d_in[7];
    const float* ku    = (const float*)d_in[8];
    const float* kvw   = (const float*)d_in[9];
    const float* vu    = (const float*)d_in[10];
    const float* vvw   = (const float*)d_in[11];
    const float* td    = (const float*)d_in[12];
    const float* out_w = (const float*)d_in[13];
    const float* out_b = (const float*)d_in[14];
    const float* ln2_g = (const float*)d_in[15];
    const float* ln2_b = (const float*)d_in[16];
    const float* w1    = (const float*)d_in[17];
    const float* b1    = (const float*)d_in[18];
    const float* w2    = (const float*)d_in[19];
    const float* b2    = (const float*)d_in[20];
    const float* adw   = (const float*)d_in[21];
    const float* adb   = (const float*)d_in[22];
    const float* auw   = (const float*)d_in[23];
    const float* aub   = (const float*)d_in[24];
    float* out = (float*)d_out;

    void* p;
#define SYM(var, sym) cudaGetSymbolAddress(&p, sym); auto* var = (decltype(&sym[0]))p
    SYM(xn,  g_xn);  SYM(x1, g_x1);  SYM(x2, g_x2);
    SYM(hlc, g_hloc); SYM(hin, g_hin);
    SYM(mixh, g_mix_h);
    SYM(qkvrh, g_qkvr_h);
    SYM(qkv,  g_qkv);
    SYM(ysh, g_ys_h);
    SYM(h2h, g_h2_h);
    SYM(ffh, g_ff_h);
    SYM(x2h, g_x2h);
    SYM(adh, g_ad_h);
    SYM(uTh, g_uT_h); SYM(uTl, g_uT_l);
    SYM(vTh, g_vT_h); SYM(vTl, g_vT_l);
    SYM(owTh, g_owT_h);
    SYM(w1Th, g_w1T_h);
    SYM(w2Th, g_w2T_h);
    SYM(adwTh, g_adwT_h); SYM(adwTl, g_adwT_l);
    SYM(auwTh, g_auwT_h);
#undef SYM
    f16* qf = qkv;
    f16* kf = qkv + (size_t)MM * CC;
    f16* vf = qkv + (size_t)2 * MM * CC;

    // variants: <BN, WM, WN, PASSES, STAGES, BIAS, GELU, RES, OUTF32, OUTH, OUTL>
    auto mm_down = mm_h<64,  4, 2, 2, 3, false, false, false, false, true,  false>;
    auto mm_up   = mm_h<128, 2, 4, 2, 2, false, false, false, false, true,  false>;
    auto mm_oprj = mm_h<128, 2, 4, 1, 3, true,  false, true,  true,  false, false>;
    auto mm_ffn1 = mm_h<128, 2, 4, 1, 3, true,  true,  false, false, true,  false>;
    auto mm_ffn2 = mm_h<128, 2, 4, 1, 3, true,  false, true,  true,  true,  false>;
    auto mm_add  = mm_h<32,  8, 1, 2, 3, true,  true,  false, false, true,  false>;
    auto mm_adu  = mm_h<128, 2, 4, 1, 2, true,  false, true,  true,  false, false>;
    cudaFuncSetAttribute(mm_down, cudaFuncAttributeMaxDynamicSharedMemorySize, SMEMSZ(2,64,3));
    cudaFuncSetAttribute(mm_up,   cudaFuncAttributeMaxDynamicSharedMemorySize, SMEMSZ(2,128,2));
    cudaFuncSetAttribute(mm_oprj, cudaFuncAttributeMaxDynamicSharedMemorySize, SMEMSZ(1,128,3));
    cudaFuncSetAttribute(mm_ffn1, cudaFuncAttributeMaxDynamicSharedMemorySize, SMEMSZ(1,128,3));
    cudaFuncSetAttribute(mm_ffn2, cudaFuncAttributeMaxDynamicSharedMemorySize, SMEMSZ(1,128,3));
    cudaFuncSetAttribute(mm_add,  cudaFuncAttributeMaxDynamicSharedMemorySize, SMEMSZ(2,32,3));
    cudaFuncSetAttribute(mm_adu,  cudaFuncAttributeMaxDynamicSharedMemorySize, SMEMSZ(1,128,2));

    dim3 tb(16, 16);
    // ---- weight transposes ----
    transpose_split3<<<dim3(RR/32, CC/32, 3), tb>>>(qu, ku, vu, CC, RR, CC,
                                                    (size_t)RR*CC, uTh, uTl);
    transpose_split3<<<dim3(CC/32, RR/32, 3), tb>>>(qv, kvw, vvw, RR, CC, RR,
                                                    (size_t)CC*RR, vTh, vTl);
    transpose_split<<<dim3(CC/32,  CC/32), tb>>>(out_w, CC, CC, CC, owTh, nullptr);
    transpose_split<<<dim3(FFD/32, CC/32), tb>>>(w1,  CC, FFD, CC,  w1Th, nullptr);
    transpose_split<<<dim3(CC/32,  FFD/32),tb>>>(w2,  FFD, CC, FFD, w2Th, nullptr);
    transpose_split<<<dim3(ARR/32, CC/32), tb>>>(adw, CC, ARR, CC,  adwTh, adwTl);
    transpose_split<<<dim3(CC/32,  64/32), tb>>>(auw, ARR, CC, 64,  auwTh, nullptr);

    // 1) xn = LN(LN(x)); mix -> fp16 (single-rounded)
    ln_kernel<<<MM, 256>>>(x, ln1_g, ln1_b, tm_g, tm_b, xn, nullptr);
    mix_split<<<MM*CC/(8*256), 256>>>(xn, mixh);

    // 2) fused low-rank down-projections (2-pass): [M,1024]@[192,1024]^T
    mm_down<<<dim3(3, MM/128), 256, SMEMSZ(2,64,3)>>>(
        MM, 3*RR, CC, CC, 3*RR, 0, 0, 0, 0,
        mixh, nullptr, uTh, uTl, nullptr, qkvrh, nullptr, nullptr, nullptr);

    // 3) batched up-projections (2-pass, z = q,k,v) -> fp16 qkv
    mm_up<<<dim3(CC/128, MM/128, 3), 256, SMEMSZ(2,128,2)>>>(
        MM, CC, RR, 3*RR, CC, RR, (size_t)CC*RR, 0, (size_t)MM*CC,
        qkvrh, nullptr, vTh, vTl, nullptr, qkv, nullptr, nullptr, nullptr);

    // 4) segmented scan (vectorized, 8 ch/thread) -> ys fp16
    scan_local  <<<SEG*BB*(CC/8)/256, 256>>>(kf, vf, td, hlc);
    scan_combine<<<BC/256, 256>>>(hlc, h0, td, hin, out, (long)out_size);
    scan_apply  <<<SEG*BB*(CC/8)/256, 256>>>(kf, vf, qf, td, hin, ysh);

    // 5) out-proj (1-pass) + bias + residual(x) -> x1 fp32
    mm_oprj<<<dim3(CC/128, MM/128), 256, SMEMSZ(1,128,3)>>>(
        MM, CC, CC, CC, 0, 0, 0, 0, 0,
        ysh, nullptr, owTh, nullptr, x1, nullptr, nullptr, out_b, x);

    // 6) h2 = LN2(x1) -> fp16
    ln_kernel<<<MM, 256>>>(x1, ln2_g, ln2_b, nullptr, nullptr, nullptr, h2h);

    // 7) FFN (1-pass)
    mm_ffn1<<<dim3(FFD/128, MM/128), 256, SMEMSZ(1,128,3)>>>(
        MM, FFD, CC, CC, FFD, 0, 0, 0, 0,
        h2h, nullptr, w1Th, nullptr, nullptr, ffh, nullptr, b1, nullptr);
    mm_ffn2<<<dim3(CC/128, MM/128), 256, SMEMSZ(1,128,3)>>>(
        MM, CC, FFD, FFD, CC, 0, 0, 0, 0,
        ffh, nullptr, w2Th, nullptr, x2, x2h, nullptr, b2, x1);

    // 8) adapter: down (2-pass, N=32 pad 64) then up (1-pass) + residual
    mm_add<<<dim3(1, MM/128), 256, SMEMSZ(2,32,3)>>>(
        MM, ARR, CC, CC, 64, 0, 0, 0, 0,
        x2h, nullptr, adwTh, adwTl, nullptr, adh, nullptr, adb, nullptr);
    mm_adu<<<dim3(CC/128, MM/128), 256, SMEMSZ(1,128,2)>>>(
        MM, CC, 64, 64, 0, 0, 0, 0, 0,
        adh, nullptr, auwTh, nullptr, out, nullptr, nullptr, aub, x2);
}